// round 6
// baseline (speedup 1.0000x reference)
#include <cuda_runtime.h>
#include <math.h>

#define BB 2
#define QQ 75
#define NN 5
#define KK 1
#define TT 196
#define CC 384
#define HH 1536
#define KT 196
#define BQ 150
#define TEMPF 10.0f

#define MCH 7          // t-chunks for mean partials (28 rows)
#define SCH 5          // t-chunks for shot/ns pass (40/36 rows)
#define HCH 8          // hidden chunks for MLP (192 units)
#define HCW 192
#define TQ 7           // t-chunk for main pass
#define NCHK 28        // TT / TQ
#define QG 15          // queries per group
#define NQG 5          // QQ / QG
#define NW 12          // warps per block (384 threads)

// ---- dynamic smem layout (floats) ----
#define OFF_SF   0                        // fshot chunk: NN*TQ*CC = 13440
#define OFF_VV   (OFF_SF + NN*TQ*CC)      // 1920
#define OFF_NSS  (OFF_VV + NN*CC)         // 35
#define OFF_SMQ  (OFF_NSS + NN*TQ)        // QG*NN*TQ = 525
#define OFF_SIM  (OFF_SMQ + QG*NN*TQ)     // 525
#define DYN_FLOATS (OFF_SIM + QG*NN*TQ)   // 16445
#define DYN_BYTES  (DYN_FLOATS * 4)

// ---------------- persistent scratch ----------------
__device__ float g_mean_part[BB*NN*MCH*CC];
__device__ float g_mlp_part[(BB + BB*NN)*HCH*CC];
__device__ float g_wt[BB*CC];
__device__ float g_wc[BB*NN*CC];
__device__ float g_ns[BB*NN*KT];
__device__ float g_shot_part[BB*NN*SCH*CC];
__device__ float g_xs_hat[BB*NN*CC];
__device__ float g_xs2_hat[BB*NN*CC];
__device__ float g_accq_part[NCHK*BQ*NN*CC];   // 32 MB
__device__ float g_mx_part[NCHK*BQ*NN];
__device__ unsigned g_bar_cnt;
__device__ unsigned g_bar_gen;

template<int NV>
__device__ __forceinline__ void warpRed(float* v) {
#pragma unroll
    for (int off = 16; off; off >>= 1) {
#pragma unroll
        for (int k = 0; k < NV; k++)
            v[k] += __shfl_xor_sync(0xffffffffu, v[k], off);
    }
}

__device__ __forceinline__ float sigm(float x) {
    return 1.0f / (1.0f + __expf(-x));
}

__device__ __forceinline__ void gridBar() {
    __syncthreads();
    if (threadIdx.x == 0) {
        __threadfence();
        unsigned gen = *(volatile unsigned*)&g_bar_gen;
        if (atomicAdd(&g_bar_cnt, 1u) == gridDim.x - 1u) {
            g_bar_cnt = 0u;
            __threadfence();
            atomicAdd(&g_bar_gen, 1u);
        } else {
            while (*(volatile unsigned*)&g_bar_gen == gen) __nanosleep(64);
        }
        __threadfence();
    }
    __syncthreads();
}

__global__ __launch_bounds__(384, 2) void kFused(
    const float* __restrict__ fshot, const float* __restrict__ fq,
    const float* __restrict__ x_shot, const float* __restrict__ xq_in,
    const float* __restrict__ w1t, const float* __restrict__ b1t,
    const float* __restrict__ w2t, const float* __restrict__ b2t,
    const float* __restrict__ w1c, const float* __restrict__ b1c,
    const float* __restrict__ w2c, const float* __restrict__ b2c,
    float* __restrict__ out) {
    extern __shared__ float dyn[];
    const int tid = threadIdx.x;
    const int w = tid >> 5, lane = tid & 31;

    // ============ Phase 1: shot mean partials + plain prototype ============
    for (int task = blockIdx.x; task < BB*NN*MCH + BB*NN; task += gridDim.x) {
        if (task < BB*NN*MCH) {
            int bn = task / MCH, ch = task % MCH;
            int t0 = ch * 28;
            const float* p = fshot + ((size_t)bn * KT + t0) * CC + tid;
            float s = 0.0f;
#pragma unroll 4
            for (int t = 0; t < 28; t++) s += p[(size_t)t * CC];
            g_mean_part[(bn * MCH + ch) * CC + tid] = s;
        } else {
            int bn = task - BB*NN*MCH;
            __syncthreads();
            float xm = x_shot[(size_t)bn * CC + tid];  // KK=1
            float r[1] = {xm * xm};
            warpRed<1>(r);
            if (lane == 0) dyn[w] = r[0];
            __syncthreads();
            float tot = 0.0f;
#pragma unroll
            for (int ww = 0; ww < NW; ww++) tot += dyn[ww];
            g_xs2_hat[bn * CC + tid] = xm / fmaxf(sqrtf(tot), 1e-12f);
            __syncthreads();
        }
    }
    gridBar();

    // ============ Phase 2: MLP partials + ns (norm of fshot rows) ============
    for (int task = blockIdx.x; task < (BB + BB*NN)*HCH + BB*NN*SCH; task += gridDim.x) {
        if (task < (BB + BB*NN)*HCH) {
            int row = task / HCH, ch = task % HCH;
            float* SX = dyn; float* HP = dyn + CC; float* HID = dyn + CC + 2*HCW;
            const float *w1, *b1, *w2;
            __syncthreads();
            if (row < BB) {
                w1 = w1t; b1 = b1t; w2 = w2t;
                float s = 0.0f;
#pragma unroll
                for (int n = 0; n < NN; n++)
#pragma unroll
                    for (int c2 = 0; c2 < MCH; c2++)
                        s += g_mean_part[((row * NN + n) * MCH + c2) * CC + tid];
                SX[tid] = s * (1.0f / (KT * NN));
            } else {
                int r = row - BB;
                w1 = w1c; b1 = b1c; w2 = w2c;
                float s = 0.0f;
#pragma unroll
                for (int c2 = 0; c2 < MCH; c2++)
                    s += g_mean_part[(r * MCH + c2) * CC + tid];
                SX[tid] = s * (1.0f / KT);
            }
            __syncthreads();

            int half = tid / HCW, jj = tid % HCW, j0 = ch * HCW;
            float h = 0.0f;
            const float* w1p = w1 + (size_t)(half * HCW) * HH + j0 + jj;
#pragma unroll 4
            for (int c = 0; c < HCW; c++) h += SX[half * HCW + c] * w1p[(size_t)c * HH];
            HP[half * HCW + jj] = h;
            __syncthreads();
            if (tid < HCW) HID[tid] = fmaxf(HP[tid] + HP[HCW + tid] + b1[j0 + tid], 0.0f);
            __syncthreads();

            float o = 0.0f;
            const float* w2p = w2 + (size_t)j0 * CC + tid;
#pragma unroll 4
            for (int j = 0; j < HCW; j++) o += HID[j] * w2p[(size_t)j * CC];
            g_mlp_part[(size_t)task * CC + tid] = o;
            __syncthreads();
        } else {
            int s2 = task - (BB + BB*NN)*HCH;
            int bn = s2 / SCH, ch = s2 % SCH;
            int t0 = ch * 40, t1 = min(KT, t0 + 40);
            for (int t = t0 + w; t < t1; t += NW) {
                const float* fp = fshot + ((size_t)bn * KT + t) * CC + 4 * lane;
                float r[1] = {0.0f};
#pragma unroll
                for (int j = 0; j < 3; j++) {
                    float4 u = *(const float4*)(fp + 128 * j);
                    r[0] += u.x*u.x + u.y*u.y + u.z*u.z + u.w*u.w;
                }
                warpRed<1>(r);
                if (lane == 0) g_ns[bn * KT + t] = sqrtf(r[0]);
            }
        }
    }
    gridBar();

    // ============ Phase 3: shot map_s partials + MLP finish ============
    for (int task = blockIdx.x; task < BB*NN*SCH + BB + BB*NN; task += gridDim.x) {
        if (task < BB*NN*SCH) {
            int bn = task / SCH, ch = task % SCH;
            int b = bn / NN;
            int t0 = ch * 40, t1 = min(KT, t0 + 40);
            float* SVV = dyn; float* PW = dyn + CC;   // PW: NW*CC per-warp partials
            __syncthreads();
            {   // vv = wc * wt reconstructed from MLP partials
                float ot = b2t[tid], oc = b2c[tid];
#pragma unroll
                for (int c2 = 0; c2 < HCH; c2++) {
                    ot += g_mlp_part[(size_t)(b * HCH + c2) * CC + tid];
                    oc += g_mlp_part[(size_t)((BB + bn) * HCH + c2) * CC + tid];
                }
                SVV[tid] = sigm(oc) * ot;
            }
            __syncthreads();

            float acc[12];
#pragma unroll
            for (int e = 0; e < 12; e++) acc[e] = 0.0f;
            for (int t = t0 + w; t < t1; t += NW) {
                const float* fp = fshot + ((size_t)bn * KT + t) * CC + 4 * lane;
                float fv[12];
#pragma unroll
                for (int j = 0; j < 3; j++) {
                    float4 u = *(const float4*)(fp + 128 * j);
                    fv[4*j] = u.x; fv[4*j+1] = u.y; fv[4*j+2] = u.z; fv[4*j+3] = u.w;
                }
                float r[1] = {0.0f};
#pragma unroll
                for (int j = 0; j < 3; j++) {
                    float4 u = *(const float4*)(&SVV[128 * j + 4 * lane]);
                    r[0] += fv[4*j]*u.x + fv[4*j+1]*u.y + fv[4*j+2]*u.z + fv[4*j+3]*u.w;
                }
                warpRed<1>(r);
                float ms = sigm(r[0]);
#pragma unroll
                for (int e = 0; e < 12; e++) acc[e] += fv[e] * ms;
            }
#pragma unroll
            for (int e = 0; e < 12; e++) {
                int c = 128 * (e >> 2) + (lane << 2) + (e & 3);
                PW[w * CC + c] = acc[e];
            }
            __syncthreads();
            float s = 0.0f;
#pragma unroll
            for (int ww = 0; ww < NW; ww++) s += PW[ww * CC + tid];
            g_shot_part[(size_t)task * CC + tid] = s;
            __syncthreads();
        } else {
            int row = task - BB*NN*SCH;
            float o = (row < BB) ? b2t[tid] : b2c[tid];
#pragma unroll
            for (int c2 = 0; c2 < HCH; c2++) o += g_mlp_part[(size_t)(row * HCH + c2) * CC + tid];
            if (row < BB) g_wt[row * CC + tid] = o;
            else          g_wc[(row - BB) * CC + tid] = sigm(o);
        }
    }
    gridBar();

    // ============ Phase 4: reweighted prototype finish + main fused pass ============
    for (int task = blockIdx.x; task < BB*NN + BB*NCHK*NQG; task += gridDim.x) {
        if (task < BB*NN) {
            int bn = task;
            __syncthreads();
            float s = 0.0f;
#pragma unroll
            for (int ch = 0; ch < SCH; ch++) s += g_shot_part[(size_t)(bn * SCH + ch) * CC + tid];
            float xsr = g_wc[bn * CC + tid] * s * (1.0f / KT);
            float r[1] = {xsr * xsr};
            warpRed<1>(r);
            if (lane == 0) dyn[w] = r[0];
            __syncthreads();
            float tot = 0.0f;
#pragma unroll
            for (int ww = 0; ww < NW; ww++) tot += dyn[ww];
            g_xs_hat[bn * CC + tid] = xsr / (1e-16f + sqrtf(tot));
            __syncthreads();
        } else {
            int m = task - BB*NN;
            int b = m / (NCHK * NQG);
            int rem = m % (NCHK * NQG);
            int chunk = rem / NQG, qg = rem % NQG;
            int t0 = chunk * TQ;
            int q0 = b * QQ + qg * QG;    // first global bq of group
            float* SF  = dyn + OFF_SF;
            float* VV  = dyn + OFF_VV;
            float* NSS = dyn + OFF_NSS;
            float* SMQ = dyn + OFF_SMQ;
            float* SIM = dyn + OFF_SIM;
            __syncthreads();
            // ---- preamble: stage fshot chunk + vv + nss into smem ----
            for (int i = tid; i < NN * TQ * (CC/4); i += 384) {
                int c4 = i % (CC/4), row = i / (CC/4);     // row = n*TQ+t
                int n = row / TQ, t = row % TQ;
                float4 u = *(const float4*)(fshot + (((size_t)(b*NN+n))*KT + t0 + t)*CC + c4*4);
                *(float4*)(SF + row*CC + c4*4) = u;
            }
            {
                float wtb = g_wt[b * CC + tid];
#pragma unroll
                for (int n = 0; n < NN; n++)
                    VV[n * CC + tid] = g_wc[(b * NN + n) * CC + tid] * wtb;
            }
            if (tid < NN * TQ) {
                int n = tid / TQ, t = tid % TQ;
                NSS[tid] = g_ns[(b * NN + n) * KT + t0 + t];
            }
            __syncthreads();

            // ---- Pass A: warp per (qi, trel) ----
            for (int it = w; it < QG * TQ; it += NW) {
                int qi = it / TQ, trel = it % TQ;
                const float* fp = fq + ((size_t)(q0 + qi) * TT + t0 + trel) * CC + 4 * lane;
                float fv[12];
#pragma unroll
                for (int j = 0; j < 3; j++) {
                    float4 u = *(const float4*)(fp + 128 * j);
                    fv[4*j] = u.x; fv[4*j+1] = u.y; fv[4*j+2] = u.z; fv[4*j+3] = u.w;
                }
                float r[11];
#pragma unroll
                for (int k = 0; k < 11; k++) r[k] = 0.0f;
#pragma unroll
                for (int e = 0; e < 12; e++) r[0] += fv[e] * fv[e];
#pragma unroll
                for (int n = 0; n < NN; n++) {
                    const float* fsp = SF + (n * TQ + trel) * CC + 4 * lane;
#pragma unroll
                    for (int j = 0; j < 3; j++) {
                        float4 u = *(const float4*)(fsp + 128 * j);
                        r[1 + n] += fv[4*j]*u.x + fv[4*j+1]*u.y + fv[4*j+2]*u.z + fv[4*j+3]*u.w;
                    }
                }
#pragma unroll
                for (int n = 0; n < NN; n++) {
                    const float* vp = VV + n * CC + 4 * lane;
#pragma unroll
                    for (int j = 0; j < 3; j++) {
                        float4 u = *(const float4*)(vp + 128 * j);
                        r[6 + n] += fv[4*j]*u.x + fv[4*j+1]*u.y + fv[4*j+2]*u.z + fv[4*j+3]*u.w;
                    }
                }
                warpRed<11>(r);
                if (lane == 0) {
                    float nq = sqrtf(r[0]);
#pragma unroll
                    for (int n = 0; n < NN; n++) {
                        float den = fmaxf(nq * NSS[n * TQ + trel], 1e-8f);
                        SIM[(qi * NN + n) * TQ + trel] = r[1 + n] / den;
                        SMQ[(qi * NN + n) * TQ + trel] = sigm(r[6 + n]);
                    }
                }
            }
            __syncthreads();

            // ---- max over trel within chunk ----
            if (tid < QG * NN) {
                int qi = tid / NN, n = tid % NN;
                float mm = -3.4e38f;
#pragma unroll
                for (int t = 0; t < TQ; t++)
                    mm = fmaxf(mm, SIM[(qi * NN + n) * TQ + t]);
                g_mx_part[((size_t)chunk * BQ + q0 + qi) * NN + n] = mm;
            }

            // ---- Pass B: thread-per-c accq partials (fq L1/L2-resident) ----
            for (int qi = 0; qi < QG; qi++) {
                float acc[NN];
#pragma unroll
                for (int n = 0; n < NN; n++) acc[n] = 0.0f;
                const float* fcol = fq + ((size_t)(q0 + qi) * TT + t0) * CC + tid;
#pragma unroll
                for (int t = 0; t < TQ; t++) {
                    float fv = fcol[(size_t)t * CC];
#pragma unroll
                    for (int n = 0; n < NN; n++)
                        acc[n] += fv * SMQ[(qi * NN + n) * TQ + t];
                }
                size_t base = ((size_t)chunk * BQ + q0 + qi) * (NN * CC);
#pragma unroll
                for (int n = 0; n < NN; n++)
                    g_accq_part[base + n * CC + tid] = acc[n];
            }
            __syncthreads();
        }
    }
    gridBar();

    // ============ Phase 5: final outputs ============
    for (int bq = blockIdx.x; bq < BQ; bq += gridDim.x) {
        int b = bq / QQ;
        float* CW = dyn; float* TOT = dyn + NW * 16;
        __syncthreads();
        if (tid == 0) {
            float s = 0.0f;
#pragma unroll
            for (int n = 0; n < NN; n++) {
                float mm = -3.4e38f;
                for (int ch = 0; ch < NCHK; ch++)
                    mm = fmaxf(mm, g_mx_part[((size_t)ch * BQ + bq) * NN + n]);
                s += mm;
            }
            s *= (1.0f / NN);
            out[bq] = s;
            out[BQ + bq] = s;
        }
        float xqv = xq_in[(size_t)bq * CC + tid];
        float pv[16];
        pv[0] = xqv * xqv;
#pragma unroll
        for (int n = 0; n < NN; n++) {
            float a = 0.0f;
#pragma unroll 7
            for (int ch = 0; ch < NCHK; ch++)
                a += g_accq_part[((size_t)ch * BQ + bq) * (NN * CC) + n * CC + tid];
            float xqr = g_wc[(b * NN + n) * CC + tid] * a * (1.0f / TT);
            pv[1 + n]  = xqv * g_xs2_hat[(b * NN + n) * CC + tid];
            pv[6 + n]  = xqr * xqr;
            pv[11 + n] = xqr * g_xs_hat[(b * NN + n) * CC + tid];
        }
        warpRed<16>(pv);
        if (lane == 0) {
#pragma unroll
            for (int k = 0; k < 16; k++) CW[w * 16 + k] = pv[k];
        }
        __syncthreads();
        if (tid < 16) {
            float s = 0.0f;
#pragma unroll
            for (int ww = 0; ww < NW; ww++) s += CW[ww * 16 + tid];
            TOT[tid] = s;
        }
        __syncthreads();
        if (tid < NN) {
            float nq2 = sqrtf(TOT[0]);
            out[2 * BQ + bq * NN + tid] = TEMPF * TOT[1 + tid] / fmaxf(nq2, 1e-12f);
            out[2 * BQ + BQ * NN + bq * NN + tid] =
                TOT[11 + tid] / (1e-16f + sqrtf(TOT[6 + tid]));
        }
        __syncthreads();
    }
}

extern "C" void kernel_launch(void* const* d_in, const int* in_sizes, int n_in,
                              void* d_out, int out_size) {
    const float* feat_shot  = (const float*)d_in[0];
    const float* feat_query = (const float*)d_in[1];
    const float* x_shot     = (const float*)d_in[2];
    const float* x_query    = (const float*)d_in[3];
    const float* w1_task    = (const float*)d_in[4];
    const float* b1_task    = (const float*)d_in[5];
    const float* w2_task    = (const float*)d_in[6];
    const float* b2_task    = (const float*)d_in[7];
    const float* w1_cls     = (const float*)d_in[8];
    const float* b1_cls     = (const float*)d_in[9];
    const float* w2_cls     = (const float*)d_in[10];
    const float* b2_cls     = (const float*)d_in[11];
    float* out = (float*)d_out;

    // Idempotent, called every time (no static guards — harness rule).
    cudaFuncSetAttribute(kFused, cudaFuncAttributeMaxDynamicSharedMemorySize, DYN_BYTES);

    int dev = 0;
    cudaGetDevice(&dev);
    int sms = 0;
    cudaDeviceGetAttribute(&sms, cudaDevAttrMultiProcessorCount, dev);
    int maxBlk = 1;
    cudaOccupancyMaxActiveBlocksPerMultiprocessor(&maxBlk, kFused, 384, DYN_BYTES);
    if (maxBlk < 1) maxBlk = 1;
    int grid = sms * maxBlk;

    kFused<<<grid, 384, DYN_BYTES>>>(feat_shot, feat_query, x_shot, x_query,
                                     w1_task, b1_task, w2_task, b2_task,
                                     w1_cls, b1_cls, w2_cls, b2_cls, out);
}

// round 8
// speedup vs baseline: 1.4167x; 1.4167x over previous
#include <cuda_runtime.h>
#include <math.h>

#define BB 2
#define QQ 75
#define NN 5
#define KK 1
#define TT 196
#define CC 384
#define HH 1536
#define KT 196
#define BQ 150
#define TEMPF 10.0f

#define MCH 7          // t-chunks for mean partials (28 rows)
#define SCH 5          // t-chunks for shot/ns pass (40/36 rows)
#define HCH 8          // hidden chunks for MLP (192 units)
#define HCW 192
#define TQ 7           // t-chunk for main pass
#define NCHK 28        // TT / TQ
#define QG 15          // queries per group
#define NQG 5          // QQ / QG
#define NW 12          // warps per block (384 threads)
#define RSTR 392       // padded row stride (floats) for SF/VV: conflict-free

// ---- dynamic smem layout (floats) ----
#define OFF_SF   0                         // fshot chunk: NN*TQ*RSTR = 13720
#define OFF_VV   (OFF_SF + NN*TQ*RSTR)     // NN*RSTR = 1960
#define OFF_NSS  (OFF_VV + NN*RSTR)        // 35
#define OFF_SIM  (OFF_NSS + NN*TQ)         // QG*NN*TQ = 525
#define DYN_FLOATS (OFF_SIM + QG*NN*TQ)    // 16240
#define DYN_BYTES  (DYN_FLOATS * 4)

// ---------------- persistent scratch ----------------
__device__ float g_mean_part[BB*NN*MCH*CC];
__device__ float g_mlp_part[(BB + BB*NN)*HCH*CC];
__device__ float g_wt[BB*CC];
__device__ float g_wc[BB*NN*CC];
__device__ float g_ns[BB*NN*KT];
__device__ float g_shot_part[BB*NN*SCH*CC];
__device__ float g_xs_hat[BB*NN*CC];
__device__ float g_xs2_hat[BB*NN*CC];
__device__ float g_smq[BQ*NN*TT];          // sigmoid map_q values (588 KB)
__device__ float g_mx_part[NCHK*BQ*NN];
__device__ unsigned g_bar_cnt;
__device__ unsigned g_bar_gen;

template<int NV>
__device__ __forceinline__ void warpRed(float* v) {
#pragma unroll
    for (int off = 16; off; off >>= 1) {
#pragma unroll
        for (int k = 0; k < NV; k++)
            v[k] += __shfl_xor_sync(0xffffffffu, v[k], off);
    }
}

// reduce within 8-lane segments
template<int NV>
__device__ __forceinline__ void segRed8(float* v) {
#pragma unroll
    for (int off = 4; off; off >>= 1) {
#pragma unroll
        for (int k = 0; k < NV; k++)
            v[k] += __shfl_xor_sync(0xffffffffu, v[k], off);
    }
}

__device__ __forceinline__ float sigm(float x) {
    return 1.0f / (1.0f + __expf(-x));
}

__device__ __forceinline__ void gridBar() {
    __syncthreads();
    if (threadIdx.x == 0) {
        __threadfence();
        unsigned gen = *(volatile unsigned*)&g_bar_gen;
        if (atomicAdd(&g_bar_cnt, 1u) == gridDim.x - 1u) {
            g_bar_cnt = 0u;
            __threadfence();
            atomicAdd(&g_bar_gen, 1u);
        } else {
            while (*(volatile unsigned*)&g_bar_gen == gen) __nanosleep(64);
        }
        __threadfence();
    }
    __syncthreads();
}

__global__ __launch_bounds__(384, 2) void kFused(
    const float* __restrict__ fshot, const float* __restrict__ fq,
    const float* __restrict__ x_shot, const float* __restrict__ xq_in,
    const float* __restrict__ w1t, const float* __restrict__ b1t,
    const float* __restrict__ w2t, const float* __restrict__ b2t,
    const float* __restrict__ w1c, const float* __restrict__ b1c,
    const float* __restrict__ w2c, const float* __restrict__ b2c,
    float* __restrict__ out) {
    extern __shared__ float dyn[];
    const int tid = threadIdx.x;
    const int w = tid >> 5, lane = tid & 31;

    // ============ Phase 1: shot mean partials + plain prototype ============
    for (int task = blockIdx.x; task < BB*NN*MCH + BB*NN; task += gridDim.x) {
        if (task < BB*NN*MCH) {
            int bn = task / MCH, ch = task % MCH;
            int t0 = ch * 28;
            const float* p = fshot + ((size_t)bn * KT + t0) * CC + tid;
            float s = 0.0f;
#pragma unroll 4
            for (int t = 0; t < 28; t++) s += p[(size_t)t * CC];
            g_mean_part[(bn * MCH + ch) * CC + tid] = s;
        } else {
            int bn = task - BB*NN*MCH;
            __syncthreads();
            float xm = x_shot[(size_t)bn * CC + tid];  // KK=1
            float r[1] = {xm * xm};
            warpRed<1>(r);
            if (lane == 0) dyn[w] = r[0];
            __syncthreads();
            float tot = 0.0f;
#pragma unroll
            for (int ww = 0; ww < NW; ww++) tot += dyn[ww];
            g_xs2_hat[bn * CC + tid] = xm / fmaxf(sqrtf(tot), 1e-12f);
            __syncthreads();
        }
    }
    gridBar();

    // ============ Phase 2: MLP partials + ns (norm of fshot rows) ============
    for (int task = blockIdx.x; task < (BB + BB*NN)*HCH + BB*NN*SCH; task += gridDim.x) {
        if (task < (BB + BB*NN)*HCH) {
            int row = task / HCH, ch = task % HCH;
            float* SX = dyn; float* HP = dyn + CC; float* HID = dyn + CC + 2*HCW;
            const float *w1, *b1, *w2;
            __syncthreads();
            if (row < BB) {
                w1 = w1t; b1 = b1t; w2 = w2t;
                float s = 0.0f;
#pragma unroll
                for (int n = 0; n < NN; n++)
#pragma unroll
                    for (int c2 = 0; c2 < MCH; c2++)
                        s += g_mean_part[((row * NN + n) * MCH + c2) * CC + tid];
                SX[tid] = s * (1.0f / (KT * NN));
            } else {
                int r = row - BB;
                w1 = w1c; b1 = b1c; w2 = w2c;
                float s = 0.0f;
#pragma unroll
                for (int c2 = 0; c2 < MCH; c2++)
                    s += g_mean_part[(r * MCH + c2) * CC + tid];
                SX[tid] = s * (1.0f / KT);
            }
            __syncthreads();

            int half = tid / HCW, jj = tid % HCW, j0 = ch * HCW;
            float h = 0.0f;
            const float* w1p = w1 + (size_t)(half * HCW) * HH + j0 + jj;
#pragma unroll 4
            for (int c = 0; c < HCW; c++) h += SX[half * HCW + c] * w1p[(size_t)c * HH];
            HP[half * HCW + jj] = h;
            __syncthreads();
            if (tid < HCW) HID[tid] = fmaxf(HP[tid] + HP[HCW + tid] + b1[j0 + tid], 0.0f);
            __syncthreads();

            float o = 0.0f;
            const float* w2p = w2 + (size_t)j0 * CC + tid;
#pragma unroll 4
            for (int j = 0; j < HCW; j++) o += HID[j] * w2p[(size_t)j * CC];
            g_mlp_part[(size_t)task * CC + tid] = o;
            __syncthreads();
        } else {
            int s2 = task - (BB + BB*NN)*HCH;
            int bn = s2 / SCH, ch = s2 % SCH;
            int t0 = ch * 40, t1 = min(KT, t0 + 40);
            for (int t = t0 + w; t < t1; t += NW) {
                const float* fp = fshot + ((size_t)bn * KT + t) * CC + 4 * lane;
                float r[1] = {0.0f};
#pragma unroll
                for (int j = 0; j < 3; j++) {
                    float4 u = *(const float4*)(fp + 128 * j);
                    r[0] += u.x*u.x + u.y*u.y + u.z*u.z + u.w*u.w;
                }
                warpRed<1>(r);
                if (lane == 0) g_ns[bn * KT + t] = sqrtf(r[0]);
            }
        }
    }
    gridBar();

    // ============ Phase 3: shot map_s partials + MLP finish ============
    for (int task = blockIdx.x; task < BB*NN*SCH + BB + BB*NN; task += gridDim.x) {
        if (task < BB*NN*SCH) {
            int bn = task / SCH, ch = task % SCH;
            int b = bn / NN;
            int t0 = ch * 40, t1 = min(KT, t0 + 40);
            float* SVV = dyn; float* PW = dyn + CC;   // PW: NW*CC per-warp partials
            __syncthreads();
            {   // vv = wc * wt reconstructed from MLP partials
                float ot = b2t[tid], oc = b2c[tid];
#pragma unroll
                for (int c2 = 0; c2 < HCH; c2++) {
                    ot += g_mlp_part[(size_t)(b * HCH + c2) * CC + tid];
                    oc += g_mlp_part[(size_t)((BB + bn) * HCH + c2) * CC + tid];
                }
                SVV[tid] = sigm(oc) * ot;
            }
            __syncthreads();

            float acc[12];
#pragma unroll
            for (int e = 0; e < 12; e++) acc[e] = 0.0f;
            for (int t = t0 + w; t < t1; t += NW) {
                const float* fp = fshot + ((size_t)bn * KT + t) * CC + 4 * lane;
                float fv[12];
#pragma unroll
                for (int j = 0; j < 3; j++) {
                    float4 u = *(const float4*)(fp + 128 * j);
                    fv[4*j] = u.x; fv[4*j+1] = u.y; fv[4*j+2] = u.z; fv[4*j+3] = u.w;
                }
                float r[1] = {0.0f};
#pragma unroll
                for (int j = 0; j < 3; j++) {
                    float4 u = *(const float4*)(&SVV[128 * j + 4 * lane]);
                    r[0] += fv[4*j]*u.x + fv[4*j+1]*u.y + fv[4*j+2]*u.z + fv[4*j+3]*u.w;
                }
                warpRed<1>(r);
                float ms = sigm(r[0]);
#pragma unroll
                for (int e = 0; e < 12; e++) acc[e] += fv[e] * ms;
            }
#pragma unroll
            for (int e = 0; e < 12; e++) {
                int c = 128 * (e >> 2) + (lane << 2) + (e & 3);
                PW[w * CC + c] = acc[e];
            }
            __syncthreads();
            float s = 0.0f;
#pragma unroll
            for (int ww = 0; ww < NW; ww++) s += PW[ww * CC + tid];
            g_shot_part[(size_t)task * CC + tid] = s;
            __syncthreads();
        } else {
            int row = task - BB*NN*SCH;
            float o = (row < BB) ? b2t[tid] : b2c[tid];
#pragma unroll
            for (int c2 = 0; c2 < HCH; c2++) o += g_mlp_part[(size_t)(row * HCH + c2) * CC + tid];
            if (row < BB) g_wt[row * CC + tid] = o;
            else          g_wc[(row - BB) * CC + tid] = sigm(o);
        }
    }
    gridBar();

    // ============ Phase 4: reweighted prototype finish + main fused pass ============
    for (int task = blockIdx.x; task < BB*NN + BB*NCHK*NQG; task += gridDim.x) {
        if (task < BB*NN) {
            int bn = task;
            __syncthreads();
            float s = 0.0f;
#pragma unroll
            for (int ch = 0; ch < SCH; ch++) s += g_shot_part[(size_t)(bn * SCH + ch) * CC + tid];
            float xsr = g_wc[bn * CC + tid] * s * (1.0f / KT);
            float r[1] = {xsr * xsr};
            warpRed<1>(r);
            if (lane == 0) dyn[w] = r[0];
            __syncthreads();
            float tot = 0.0f;
#pragma unroll
            for (int ww = 0; ww < NW; ww++) tot += dyn[ww];
            g_xs_hat[bn * CC + tid] = xsr / (1e-16f + sqrtf(tot));
            __syncthreads();
        } else {
            int m = task - BB*NN;
            int b = m / (NCHK * NQG);
            int rem = m % (NCHK * NQG);
            int chunk = rem / NQG, qg = rem % NQG;
            int t0 = chunk * TQ;
            int q0 = b * QQ + qg * QG;    // first global bq of group
            float* SF  = dyn + OFF_SF;
            float* VV  = dyn + OFF_VV;
            float* NSS = dyn + OFF_NSS;
            float* SIM = dyn + OFF_SIM;
            __syncthreads();
            // ---- preamble: stage fshot chunk (stride RSTR) + vv + nss ----
            for (int i = tid; i < NN * TQ * (CC/4); i += 384) {
                int c4 = i % (CC/4), row = i / (CC/4);     // row = n*TQ+t
                int n = row / TQ, t = row % TQ;
                float4 u = *(const float4*)(fshot + (((size_t)(b*NN+n))*KT + t0 + t)*CC + c4*4);
                *(float4*)(SF + row*RSTR + c4*4) = u;
            }
            {
                float wtb = g_wt[b * CC + tid];
#pragma unroll
                for (int n = 0; n < NN; n++)
                    VV[n * RSTR + tid] = g_wc[(b * NN + n) * CC + tid] * wtb;
            }
            if (tid < NN * TQ) {
                int n = tid / TQ, t = tid % TQ;
                NSS[tid] = g_ns[(b * NN + n) * KT + t0 + t];
            }
            __syncthreads();

            // ---- Pass A: 4 items per warp, 8 lanes per item ----
            // items enumerated t-major: item = trel*QG + qi (4 consecutive items
            // share trel -> SF/VV rows broadcast across groups)
            const int g8 = lane >> 3, l8 = lane & 7;
            for (int base = w * 4; base < QG * TQ; base += NW * 4) {
                int item = base + g8;
                bool valid = item < QG * TQ;
                int it = valid ? item : QG * TQ - 1;
                int trel = it / QG, qi = it % QG;
                const float* fp = fq + ((size_t)(q0 + qi) * TT + t0 + trel) * CC + l8 * 4;
                float r[11];
#pragma unroll
                for (int k = 0; k < 11; k++) r[k] = 0.0f;
#pragma unroll 3
                for (int i = 0; i < 12; i++) {
                    float4 a = *(const float4*)(fp + i * 32);
                    r[0] += a.x*a.x + a.y*a.y + a.z*a.z + a.w*a.w;
#pragma unroll
                    for (int n = 0; n < NN; n++) {
                        float4 u = *(const float4*)(SF + (n * TQ + trel) * RSTR + i * 32 + l8 * 4);
                        r[1 + n] += a.x*u.x + a.y*u.y + a.z*u.z + a.w*u.w;
                        float4 v = *(const float4*)(VV + n * RSTR + i * 32 + l8 * 4);
                        r[6 + n] += a.x*v.x + a.y*v.y + a.z*v.z + a.w*v.w;
                    }
                }
                segRed8<11>(r);
                if (l8 == 0 && valid) {
                    float nq = sqrtf(r[0]);
#pragma unroll
                    for (int n = 0; n < NN; n++) {
                        float den = fmaxf(nq * NSS[n * TQ + trel], 1e-8f);
                        SIM[(qi * NN + n) * TQ + trel] = r[1 + n] / den;
                        g_smq[((size_t)(q0 + qi) * NN + n) * TT + t0 + trel] = sigm(r[6 + n]);
                    }
                }
            }
            __syncthreads();

            // ---- max over trel within chunk ----
            if (tid < QG * NN) {
                int qi = tid / NN, n = tid % NN;
                float mm = -3.4e38f;
#pragma unroll
                for (int t = 0; t < TQ; t++)
                    mm = fmaxf(mm, SIM[(qi * NN + n) * TQ + t]);
                g_mx_part[((size_t)chunk * BQ + q0 + qi) * NN + n] = mm;
            }
            __syncthreads();
        }
    }
    gridBar();

    // ============ Phase 5: accq from fq re-stream + final outputs ============
    for (int bq = blockIdx.x; bq < BQ; bq += gridDim.x) {
        int b = bq / QQ;
        float* SMQ5 = dyn;                    // NN*TT = 980
        float* CW = dyn + NN*TT;              // NW*16
        float* TOT = CW + NW*16;
        __syncthreads();
        for (int i = tid; i < NN * TT; i += 384)
            SMQ5[i] = g_smq[(size_t)bq * NN * TT + i];
        __syncthreads();

        if (tid == 0) {
            float s = 0.0f;
#pragma unroll
            for (int n = 0; n < NN; n++) {
                float mm = -3.4e38f;
                for (int ch = 0; ch < NCHK; ch++)
                    mm = fmaxf(mm, g_mx_part[((size_t)ch * BQ + bq) * NN + n]);
                s += mm;
            }
            s *= (1.0f / NN);
            out[bq] = s;
            out[BQ + bq] = s;
        }

        // accq[n][c=tid] = sum_t fq[t,c] * smq[n,t]
        float acc[NN];
#pragma unroll
        for (int n = 0; n < NN; n++) acc[n] = 0.0f;
        const float* fcol = fq + (size_t)bq * TT * CC + tid;
#pragma unroll 4
        for (int t = 0; t < TT; t++) {
            float fv = fcol[(size_t)t * CC];
#pragma unroll
            for (int n = 0; n < NN; n++)
                acc[n] += fv * SMQ5[n * TT + t];
        }

        float xqv = xq_in[(size_t)bq * CC + tid];
        float pv[16];
        pv[0] = xqv * xqv;
#pragma unroll
        for (int n = 0; n < NN; n++) {
            float xqr = g_wc[(b * NN + n) * CC + tid] * acc[n] * (1.0f / TT);
            pv[1 + n]  = xqv * g_xs2_hat[(b * NN + n) * CC + tid];
            pv[6 + n]  = xqr * xqr;
            pv[11 + n] = xqr * g_xs_hat[(b * NN + n) * CC + tid];
        }
        warpRed<16>(pv);
        if (lane == 0) {
#pragma unroll
            for (int k = 0; k < 16; k++) CW[w * 16 + k] = pv[k];
        }
        __syncthreads();
        if (tid < 16) {
            float s = 0.0f;
#pragma unroll
            for (int ww = 0; ww < NW; ww++) s += CW[ww * 16 + tid];
            TOT[tid] = s;
        }
        __syncthreads();
        if (tid < NN) {
            float nq2 = sqrtf(TOT[0]);
            out[2 * BQ + bq * NN + tid] = TEMPF * TOT[1 + tid] / fmaxf(nq2, 1e-12f);
            out[2 * BQ + BQ * NN + bq * NN + tid] =
                TOT[11 + tid] / (1e-16f + sqrtf(TOT[6 + tid]));
        }
        __syncthreads();
    }
}

extern "C" void kernel_launch(void* const* d_in, const int* in_sizes, int n_in,
                              void* d_out, int out_size) {
    const float* feat_shot  = (const float*)d_in[0];
    const float* feat_query = (const float*)d_in[1];
    const float* x_shot     = (const float*)d_in[2];
    const float* x_query    = (const float*)d_in[3];
    const float* w1_task    = (const float*)d_in[4];
    const float* b1_task    = (const float*)d_in[5];
    const float* w2_task    = (const float*)d_in[6];
    const float* b2_task    = (const float*)d_in[7];
    const float* w1_cls     = (const float*)d_in[8];
    const float* b1_cls     = (const float*)d_in[9];
    const float* w2_cls     = (const float*)d_in[10];
    const float* b2_cls     = (const float*)d_in[11];
    float* out = (float*)d_out;

    // Idempotent, called every time (no static guards — harness rule).
    cudaFuncSetAttribute(kFused, cudaFuncAttributeMaxDynamicSharedMemorySize, DYN_BYTES);

    int dev = 0;
    cudaGetDevice(&dev);
    int sms = 0;
    cudaDeviceGetAttribute(&sms, cudaDevAttrMultiProcessorCount, dev);
    int maxBlk = 1;
    cudaOccupancyMaxActiveBlocksPerMultiprocessor(&maxBlk, kFused, 384, DYN_BYTES);
    if (maxBlk < 1) maxBlk = 1;
    int grid = sms * maxBlk;

    kFused<<<grid, 384, DYN_BYTES>>>(feat_shot, feat_query, x_shot, x_query,
                                     w1_task, b1_task, w2_task, b2_task,
                                     w1_cls, b1_cls, w2_cls, b2_cls, out);
}

// round 9
// speedup vs baseline: 1.6383x; 1.1564x over previous
#include <cuda_runtime.h>
#include <math.h>

#define BB 2
#define QQ 75
#define NN 5
#define KK 1
#define TT 196
#define CC 384
#define HH 1536
#define KT 196
#define BQ 150
#define TEMPF 10.0f

#define MCH 7          // t-chunks for mean partials (28 rows)
#define NSCH 10        // t-chunks for ns pass (20 rows)
#define SCH 5          // t-chunks for shot map_s pass (40/36 rows)
#define HCH 16         // hidden chunks for MLP (96 units)
#define HCW 96
#define TQ 7           // t-chunk for main pass
#define NCHK 28        // TT / TQ
#define QG 25          // queries per group
#define NQG 3          // QQ / QG
#define NW 12          // warps per block (384 threads)
#define RSTR 392       // padded row stride (floats) for SF/VV

// ---- dynamic smem layout (floats) ----
#define OFF_SF   0                         // NN*TQ*RSTR = 13720
#define OFF_VV   (OFF_SF + NN*TQ*RSTR)     // NN*RSTR = 1960
#define OFF_NSS  (OFF_VV + NN*RSTR)        // NN*TQ = 35
#define OFF_SIM  (OFF_NSS + NN*TQ)         // QG*NN*TQ = 875
#define DYN_FLOATS (OFF_SIM + QG*NN*TQ)    // 16590
#define DYN_BYTES  (DYN_FLOATS * 4)

// ---------------- persistent scratch ----------------
__device__ float g_mean_part[BB*NN*MCH*CC];
__device__ float g_mlp_part[(BB + BB*NN)*HCH*CC];
__device__ float g_wt[BB*CC];
__device__ float g_wc[BB*NN*CC];
__device__ float g_ns[BB*NN*KT];
__device__ float g_shot_part[BB*NN*SCH*CC];
__device__ float g_xs2_hat[BB*NN*CC];
__device__ float g_smq[BQ*NN*TT];
__device__ float g_mx_part[NCHK*BQ*NN];
__device__ unsigned g_bar_cnt;
__device__ unsigned g_bar_gen;

template<int NV>
__device__ __forceinline__ void warpRed(float* v) {
#pragma unroll
    for (int off = 16; off; off >>= 1) {
#pragma unroll
        for (int k = 0; k < NV; k++)
            v[k] += __shfl_xor_sync(0xffffffffu, v[k], off);
    }
}

template<int NV>
__device__ __forceinline__ void segRed8(float* v) {
#pragma unroll
    for (int off = 4; off; off >>= 1) {
#pragma unroll
        for (int k = 0; k < NV; k++)
            v[k] += __shfl_xor_sync(0xffffffffu, v[k], off);
    }
}

__device__ __forceinline__ float sigm(float x) {
    return 1.0f / (1.0f + __expf(-x));
}

__device__ __forceinline__ void gridBar() {
    __syncthreads();
    if (threadIdx.x == 0) {
        __threadfence();
        unsigned gen = *(volatile unsigned*)&g_bar_gen;
        if (atomicAdd(&g_bar_cnt, 1u) == gridDim.x - 1u) {
            g_bar_cnt = 0u;
            __threadfence();
            atomicAdd(&g_bar_gen, 1u);
        } else {
            while (*(volatile unsigned*)&g_bar_gen == gen) __nanosleep(64);
        }
        __threadfence();
    }
    __syncthreads();
}

__global__ __launch_bounds__(384, 2) void kFused(
    const float* __restrict__ fshot, const float* __restrict__ fq,
    const float* __restrict__ x_shot, const float* __restrict__ xq_in,
    const float* __restrict__ w1t, const float* __restrict__ b1t,
    const float* __restrict__ w2t, const float* __restrict__ b2t,
    const float* __restrict__ w1c, const float* __restrict__ b1c,
    const float* __restrict__ w2c, const float* __restrict__ b2c,
    float* __restrict__ out) {
    extern __shared__ float dyn[];
    const int tid = threadIdx.x;
    const int w = tid >> 5, lane = tid & 31;

    // ===== Phase 1: mean partials + ns + plain prototype =====
    for (int task = blockIdx.x; task < BB*NN*MCH + BB*NN*NSCH + BB*NN; task += gridDim.x) {
        if (task < BB*NN*MCH) {
            int bn = task / MCH, ch = task % MCH;
            int t0 = ch * 28;
            const float* p = fshot + ((size_t)bn * KT + t0) * CC + tid;
            float s = 0.0f;
#pragma unroll 4
            for (int t = 0; t < 28; t++) s += p[(size_t)t * CC];
            g_mean_part[(bn * MCH + ch) * CC + tid] = s;
        } else if (task < BB*NN*MCH + BB*NN*NSCH) {
            int s2 = task - BB*NN*MCH;
            int bn = s2 / NSCH, ch = s2 % NSCH;
            int t0 = ch * 20, t1 = min(KT, t0 + 20);
            for (int t = t0 + w; t < t1; t += NW) {
                const float* fp = fshot + ((size_t)bn * KT + t) * CC + 4 * lane;
                float r[1] = {0.0f};
#pragma unroll
                for (int j = 0; j < 3; j++) {
                    float4 u = *(const float4*)(fp + 128 * j);
                    r[0] += u.x*u.x + u.y*u.y + u.z*u.z + u.w*u.w;
                }
                warpRed<1>(r);
                if (lane == 0) g_ns[bn * KT + t] = sqrtf(r[0]);
            }
        } else {
            int bn = task - BB*NN*MCH - BB*NN*NSCH;
            __syncthreads();
            float xm = x_shot[(size_t)bn * CC + tid];  // KK=1
            float r[1] = {xm * xm};
            warpRed<1>(r);
            if (lane == 0) dyn[w] = r[0];
            __syncthreads();
            float tot = 0.0f;
#pragma unroll
            for (int ww = 0; ww < NW; ww++) tot += dyn[ww];
            g_xs2_hat[bn * CC + tid] = xm / fmaxf(sqrtf(tot), 1e-12f);
            __syncthreads();
        }
    }
    gridBar();

    // ===== Phase 2: MLP partials (12 rows x 16 hidden chunks) =====
    for (int task = blockIdx.x; task < (BB + BB*NN) * HCH; task += gridDim.x) {
        int row = task / HCH, ch = task % HCH;
        float* SX = dyn; float* HP = dyn + CC; float* HID = dyn + 2*CC;
        const float *w1, *b1, *w2;
        __syncthreads();
        if (row < BB) {
            w1 = w1t; b1 = b1t; w2 = w2t;
            float s = 0.0f;
#pragma unroll
            for (int n = 0; n < NN; n++)
#pragma unroll
                for (int c2 = 0; c2 < MCH; c2++)
                    s += g_mean_part[((row * NN + n) * MCH + c2) * CC + tid];
            SX[tid] = s * (1.0f / (KT * NN));
        } else {
            int r = row - BB;
            w1 = w1c; b1 = b1c; w2 = w2c;
            float s = 0.0f;
#pragma unroll
            for (int c2 = 0; c2 < MCH; c2++)
                s += g_mean_part[(r * MCH + c2) * CC + tid];
            SX[tid] = s * (1.0f / KT);
        }
        __syncthreads();

        int half = tid / HCW, jj = tid % HCW, j0 = ch * HCW;  // half in 0..3
        float h = 0.0f;
        const float* w1p = w1 + (size_t)(half * HCW) * HH + j0 + jj;
#pragma unroll 4
        for (int c = 0; c < HCW; c++) h += SX[half * HCW + c] * w1p[(size_t)c * HH];
        HP[tid] = h;
        __syncthreads();
        if (tid < HCW)
            HID[tid] = fmaxf(HP[tid] + HP[HCW + tid] + HP[2*HCW + tid] + HP[3*HCW + tid]
                             + b1[j0 + tid], 0.0f);
        __syncthreads();

        float o = 0.0f;
        const float* w2p = w2 + (size_t)j0 * CC + tid;
#pragma unroll 4
        for (int j = 0; j < HCW; j++) o += HID[j] * w2p[(size_t)j * CC];
        g_mlp_part[(size_t)task * CC + tid] = o;
        __syncthreads();
    }
    gridBar();

    // ===== Phase 3: main fused pass + shot map_s pass + MLP finish =====
    for (int task = blockIdx.x; task < BB*NCHK*NQG + BB*NN*SCH + BB + BB*NN; task += gridDim.x) {
        if (task < BB*NCHK*NQG) {
            int b = task / (NCHK * NQG);
            int rem = task % (NCHK * NQG);
            int chunk = rem / NQG, qg = rem % NQG;
            int t0 = chunk * TQ;
            int q0 = b * QQ + qg * QG;
            float* SF  = dyn + OFF_SF;
            float* VV  = dyn + OFF_VV;
            float* NSS = dyn + OFF_NSS;
            float* SIM = dyn + OFF_SIM;
            __syncthreads();
            // stage fshot chunk
            for (int i = tid; i < NN * TQ * (CC/4); i += 384) {
                int c4 = i % (CC/4), row = i / (CC/4);
                int n = row / TQ, t = row % TQ;
                float4 u = *(const float4*)(fshot + (((size_t)(b*NN+n))*KT + t0 + t)*CC + c4*4);
                *(float4*)(SF + row*RSTR + c4*4) = u;
            }
            // reconstruct vv = sigm(mlp_cls)*mlp_task from partials (race-free)
            {
                float ot = b2t[tid];
#pragma unroll
                for (int c2 = 0; c2 < HCH; c2++)
                    ot += g_mlp_part[(size_t)(b * HCH + c2) * CC + tid];
#pragma unroll
                for (int n = 0; n < NN; n++) {
                    float oc = b2c[tid];
#pragma unroll
                    for (int c2 = 0; c2 < HCH; c2++)
                        oc += g_mlp_part[(size_t)((BB + b*NN + n) * HCH + c2) * CC + tid];
                    VV[n * RSTR + tid] = sigm(oc) * ot;
                }
            }
            if (tid < NN * TQ) {
                int n = tid / TQ, t = tid % TQ;
                NSS[tid] = g_ns[(b * NN + n) * KT + t0 + t];
            }
            __syncthreads();

            // Pass A: 4 items per warp, 8 lanes per item, t-major enumeration
            const int g8 = lane >> 3, l8 = lane & 7;
            for (int base = w * 4; base < QG * TQ; base += NW * 4) {
                int item = base + g8;
                bool valid = item < QG * TQ;
                int it = valid ? item : QG * TQ - 1;
                int trel = it / QG, qi = it % QG;
                const float* fp = fq + ((size_t)(q0 + qi) * TT + t0 + trel) * CC + l8 * 4;
                float r[11];
#pragma unroll
                for (int k = 0; k < 11; k++) r[k] = 0.0f;
#pragma unroll 3
                for (int i = 0; i < 12; i++) {
                    float4 a = *(const float4*)(fp + i * 32);
                    r[0] += a.x*a.x + a.y*a.y + a.z*a.z + a.w*a.w;
#pragma unroll
                    for (int n = 0; n < NN; n++) {
                        float4 u = *(const float4*)(SF + (n * TQ + trel) * RSTR + i * 32 + l8 * 4);
                        r[1 + n] += a.x*u.x + a.y*u.y + a.z*u.z + a.w*u.w;
                        float4 v = *(const float4*)(VV + n * RSTR + i * 32 + l8 * 4);
                        r[6 + n] += a.x*v.x + a.y*v.y + a.z*v.z + a.w*v.w;
                    }
                }
                segRed8<11>(r);
                if (l8 == 0 && valid) {
                    float nq = sqrtf(r[0]);
#pragma unroll
                    for (int n = 0; n < NN; n++) {
                        float den = fmaxf(nq * NSS[n * TQ + trel], 1e-8f);
                        SIM[(qi * NN + n) * TQ + trel] = r[1 + n] / den;
                        g_smq[((size_t)(q0 + qi) * NN + n) * TT + t0 + trel] = sigm(r[6 + n]);
                    }
                }
            }
            __syncthreads();

            if (tid < QG * NN) {
                int qi = tid / NN, n = tid % NN;
                float mm = -3.4e38f;
#pragma unroll
                for (int t = 0; t < TQ; t++)
                    mm = fmaxf(mm, SIM[(qi * NN + n) * TQ + t]);
                g_mx_part[((size_t)chunk * BQ + q0 + qi) * NN + n] = mm;
            }
            __syncthreads();
        } else if (task < BB*NCHK*NQG + BB*NN*SCH) {
            int s2 = task - BB*NCHK*NQG;
            int bn = s2 / SCH, ch = s2 % SCH;
            int b = bn / NN;
            int t0 = ch * 40, t1 = min(KT, t0 + 40);
            float* SVV = dyn; float* PW = dyn + CC;
            __syncthreads();
            {
                float ot = b2t[tid], oc = b2c[tid];
#pragma unroll
                for (int c2 = 0; c2 < HCH; c2++) {
                    ot += g_mlp_part[(size_t)(b * HCH + c2) * CC + tid];
                    oc += g_mlp_part[(size_t)((BB + bn) * HCH + c2) * CC + tid];
                }
                SVV[tid] = sigm(oc) * ot;
            }
            __syncthreads();

            float acc[12];
#pragma unroll
            for (int e = 0; e < 12; e++) acc[e] = 0.0f;
            for (int t = t0 + w; t < t1; t += NW) {
                const float* fp = fshot + ((size_t)bn * KT + t) * CC + 4 * lane;
                float fv[12];
#pragma unroll
                for (int j = 0; j < 3; j++) {
                    float4 u = *(const float4*)(fp + 128 * j);
                    fv[4*j] = u.x; fv[4*j+1] = u.y; fv[4*j+2] = u.z; fv[4*j+3] = u.w;
                }
                float r[1] = {0.0f};
#pragma unroll
                for (int j = 0; j < 3; j++) {
                    float4 u = *(const float4*)(&SVV[128 * j + 4 * lane]);
                    r[0] += fv[4*j]*u.x + fv[4*j+1]*u.y + fv[4*j+2]*u.z + fv[4*j+3]*u.w;
                }
                warpRed<1>(r);
                float ms = sigm(r[0]);
#pragma unroll
                for (int e = 0; e < 12; e++) acc[e] += fv[e] * ms;
            }
#pragma unroll
            for (int e = 0; e < 12; e++) {
                int c = 128 * (e >> 2) + (lane << 2) + (e & 3);
                PW[w * CC + c] = acc[e];
            }
            __syncthreads();
            float s = 0.0f;
#pragma unroll
            for (int ww = 0; ww < NW; ww++) s += PW[ww * CC + tid];
            g_shot_part[(size_t)s2 * CC + tid] = s;
            __syncthreads();
        } else {
            int row = task - BB*NCHK*NQG - BB*NN*SCH;
            float o = (row < BB) ? b2t[tid] : b2c[tid];
#pragma unroll
            for (int c2 = 0; c2 < HCH; c2++) o += g_mlp_part[(size_t)(row * HCH + c2) * CC + tid];
            if (row < BB) g_wt[row * CC + tid] = o;
            else          g_wc[(row - BB) * CC + tid] = sigm(o);
        }
    }
    gridBar();

    // ===== Phase 4: accq from fq re-stream + inline xsr + final outputs =====
    for (int bq = blockIdx.x; bq < BQ; bq += gridDim.x) {
        int b = bq / QQ;
        float* SMQ5 = dyn;                    // NN*TT = 980
        float* CW = dyn + NN*TT;              // NW*21
        float* TOT = CW + NW*21;
        __syncthreads();
        for (int i = tid; i < NN * TT; i += 384)
            SMQ5[i] = g_smq[(size_t)bq * NN * TT + i];
        __syncthreads();

        if (tid == 0) {
            float s = 0.0f;
#pragma unroll
            for (int n = 0; n < NN; n++) {
                float mm = -3.4e38f;
                for (int ch = 0; ch < NCHK; ch++)
                    mm = fmaxf(mm, g_mx_part[((size_t)ch * BQ + bq) * NN + n]);
                s += mm;
            }
            s *= (1.0f / NN);
            out[bq] = s;
            out[BQ + bq] = s;
        }

        float acc[NN];
#pragma unroll
        for (int n = 0; n < NN; n++) acc[n] = 0.0f;
        const float* fcol = fq + (size_t)bq * TT * CC + tid;
#pragma unroll 4
        for (int t = 0; t < TT; t++) {
            float fv = fcol[(size_t)t * CC];
#pragma unroll
            for (int n = 0; n < NN; n++)
                acc[n] += fv * SMQ5[n * TT + t];
        }

        float xqv = xq_in[(size_t)bq * CC + tid];
        float pv[21];
        pv[0] = xqv * xqv;
#pragma unroll
        for (int n = 0; n < NN; n++) {
            float wcv = g_wc[(b * NN + n) * CC + tid];
            float sp = 0.0f;
#pragma unroll
            for (int ch = 0; ch < SCH; ch++)
                sp += g_shot_part[(size_t)((b * NN + n) * SCH + ch) * CC + tid];
            float xsr = wcv * sp * (1.0f / KT);
            float xqr = wcv * acc[n] * (1.0f / TT);
            pv[1 + n]  = xqv * g_xs2_hat[(b * NN + n) * CC + tid];
            pv[6 + n]  = xqr * xqr;
            pv[11 + n] = xqr * xsr;
            pv[16 + n] = xsr * xsr;
        }
        warpRed<21>(pv);
        if (lane == 0) {
#pragma unroll
            for (int k = 0; k < 21; k++) CW[w * 21 + k] = pv[k];
        }
        __syncthreads();
        if (tid < 21) {
            float s = 0.0f;
#pragma unroll
            for (int ww = 0; ww < NW; ww++) s += CW[ww * 21 + tid];
            TOT[tid] = s;
        }
        __syncthreads();
        if (tid < NN) {
            float nq2 = fmaxf(sqrtf(TOT[0]), 1e-12f);
            out[2 * BQ + bq * NN + tid] = TEMPF * TOT[1 + tid] / nq2;
            out[2 * BQ + BQ * NN + bq * NN + tid] =
                TOT[11 + tid] / ((1e-16f + sqrtf(TOT[6 + tid])) * (1e-16f + sqrtf(TOT[16 + tid])));
        }
        __syncthreads();
    }
}

extern "C" void kernel_launch(void* const* d_in, const int* in_sizes, int n_in,
                              void* d_out, int out_size) {
    const float* feat_shot  = (const float*)d_in[0];
    const float* feat_query = (const float*)d_in[1];
    const float* x_shot     = (const float*)d_in[2];
    const float* x_query    = (const float*)d_in[3];
    const float* w1_task    = (const float*)d_in[4];
    const float* b1_task    = (const float*)d_in[5];
    const float* w2_task    = (const float*)d_in[6];
    const float* b2_task    = (const float*)d_in[7];
    const float* w1_cls     = (const float*)d_in[8];
    const float* b1_cls     = (const float*)d_in[9];
    const float* w2_cls     = (const float*)d_in[10];
    const float* b2_cls     = (const float*)d_in[11];
    float* out = (float*)d_out;

    cudaFuncSetAttribute(kFused, cudaFuncAttributeMaxDynamicSharedMemorySize, DYN_BYTES);

    int dev = 0;
    cudaGetDevice(&dev);
    int sms = 0;
    cudaDeviceGetAttribute(&sms, cudaDevAttrMultiProcessorCount, dev);
    int maxBlk = 1;
    cudaOccupancyMaxActiveBlocksPerMultiprocessor(&maxBlk, kFused, 384, DYN_BYTES);
    if (maxBlk < 1) maxBlk = 1;
    int grid = sms * maxBlk;

    kFused<<<grid, 384, DYN_BYTES>>>(feat_shot, feat_query, x_shot, x_query,
                                     w1_task, b1_task, w2_task, b2_task,
                                     w1_cls, b1_cls, w2_cls, b2_cls, out);
}

// round 10
// speedup vs baseline: 1.6618x; 1.0143x over previous
#include <cuda_runtime.h>
#include <math.h>

#define BB 2
#define QQ 75
#define NN 5
#define KK 1
#define TT 196
#define CC 384
#define HH 1536
#define KT 196
#define BQ 150
#define TEMPF 10.0f

#define MCH 7          // t-chunks for mean partials (28 rows)
#define NSCH 10        // t-chunks for ns pass (20 rows)
#define SCH 5          // t-chunks for shot map_s pass (40/36 rows)
#define HCH 16         // hidden chunks for MLP (96 units)
#define HCW 96
#define TQ 7           // t-chunk for main pass
#define NCHK 28        // TT / TQ
#define QG 25          // queries per group
#define NQG 3          // QQ / QG
#define NW 12          // warps per block (384 threads)
#define RSTR 392       // padded row stride (floats) for SF/VV

// ---- dynamic smem layout (floats) ----
#define OFF_SF   0                         // NN*TQ*RSTR = 13720
#define OFF_VV   (OFF_SF + NN*TQ*RSTR)     // NN*RSTR = 1960
#define OFF_NSS  (OFF_VV + NN*RSTR)        // NN*TQ = 35
#define OFF_SIM  (OFF_NSS + NN*TQ)         // QG*NN*TQ = 875
#define DYN_FLOATS (OFF_SIM + QG*NN*TQ)    // 16590
#define DYN_BYTES  (DYN_FLOATS * 4)

typedef unsigned long long u64;

// ---------------- persistent scratch ----------------
__device__ float g_mean_part[BB*NN*MCH*CC];
__device__ float g_mlp_part[(BB + BB*NN)*HCH*CC];
__device__ float g_wt[BB*CC];
__device__ float g_wc[BB*NN*CC];
__device__ float g_ns[BB*NN*KT];
__device__ float g_shot_part[BB*NN*SCH*CC];
__device__ float g_xs2_hat[BB*NN*CC];
__device__ float g_smq[BQ*NN*TT];
__device__ float g_mx_part[NCHK*BQ*NN];
__device__ unsigned g_bar_cnt;
__device__ unsigned g_bar_gen;

template<int NV>
__device__ __forceinline__ void warpRed(float* v) {
#pragma unroll
    for (int off = 16; off; off >>= 1) {
#pragma unroll
        for (int k = 0; k < NV; k++)
            v[k] += __shfl_xor_sync(0xffffffffu, v[k], off);
    }
}

template<int NV>
__device__ __forceinline__ void segRed8(float* v) {
#pragma unroll
    for (int off = 4; off; off >>= 1) {
#pragma unroll
        for (int k = 0; k < NV; k++)
            v[k] += __shfl_xor_sync(0xffffffffu, v[k], off);
    }
}

// packed f32x2 FMA: d += a * b (elementwise on the two packed floats)
__device__ __forceinline__ void ffma2(u64& d, u64 a, u64 b) {
    asm("fma.rn.f32x2 %0, %1, %2, %0;" : "+l"(d) : "l"(a), "l"(b));
}
__device__ __forceinline__ float upsum(u64 v) {
    float lo, hi;
    asm("mov.b64 {%0, %1}, %2;" : "=f"(lo), "=f"(hi) : "l"(v));
    return lo + hi;
}
__device__ __forceinline__ u64 pk2(float a, float b) {
    u64 r;
    asm("mov.b64 %0, {%1, %2};" : "=l"(r) : "f"(a), "f"(b));
    return r;
}

__device__ __forceinline__ float sigm(float x) {
    return 1.0f / (1.0f + __expf(-x));
}

__device__ __forceinline__ void gridBar() {
    __syncthreads();
    if (threadIdx.x == 0) {
        __threadfence();
        unsigned gen = *(volatile unsigned*)&g_bar_gen;
        if (atomicAdd(&g_bar_cnt, 1u) == gridDim.x - 1u) {
            g_bar_cnt = 0u;
            __threadfence();
            atomicAdd(&g_bar_gen, 1u);
        } else {
            while (*(volatile unsigned*)&g_bar_gen == gen) __nanosleep(64);
        }
        __threadfence();
    }
    __syncthreads();
}

__global__ __launch_bounds__(384, 2) void kFused(
    const float* __restrict__ fshot, const float* __restrict__ fq,
    const float* __restrict__ x_shot, const float* __restrict__ xq_in,
    const float* __restrict__ w1t, const float* __restrict__ b1t,
    const float* __restrict__ w2t, const float* __restrict__ b2t,
    const float* __restrict__ w1c, const float* __restrict__ b1c,
    const float* __restrict__ w2c, const float* __restrict__ b2c,
    float* __restrict__ out) {
    extern __shared__ float dyn[];
    const int tid = threadIdx.x;
    const int w = tid >> 5, lane = tid & 31;

    // ===== Phase 1: mean partials + ns + plain prototype =====
    for (int task = blockIdx.x; task < BB*NN*MCH + BB*NN*NSCH + BB*NN; task += gridDim.x) {
        if (task < BB*NN*MCH) {
            int bn = task / MCH, ch = task % MCH;
            int t0 = ch * 28;
            const float* p = fshot + ((size_t)bn * KT + t0) * CC + tid;
            float s = 0.0f;
#pragma unroll 4
            for (int t = 0; t < 28; t++) s += p[(size_t)t * CC];
            g_mean_part[(bn * MCH + ch) * CC + tid] = s;
        } else if (task < BB*NN*MCH + BB*NN*NSCH) {
            int s2 = task - BB*NN*MCH;
            int bn = s2 / NSCH, ch = s2 % NSCH;
            int t0 = ch * 20, t1 = min(KT, t0 + 20);
            for (int t = t0 + w; t < t1; t += NW) {
                const float* fp = fshot + ((size_t)bn * KT + t) * CC + 4 * lane;
                float r[1] = {0.0f};
#pragma unroll
                for (int j = 0; j < 3; j++) {
                    float4 u = *(const float4*)(fp + 128 * j);
                    r[0] += u.x*u.x + u.y*u.y + u.z*u.z + u.w*u.w;
                }
                warpRed<1>(r);
                if (lane == 0) g_ns[bn * KT + t] = sqrtf(r[0]);
            }
        } else {
            int bn = task - BB*NN*MCH - BB*NN*NSCH;
            __syncthreads();
            float xm = x_shot[(size_t)bn * CC + tid];  // KK=1
            float r[1] = {xm * xm};
            warpRed<1>(r);
            if (lane == 0) dyn[w] = r[0];
            __syncthreads();
            float tot = 0.0f;
#pragma unroll
            for (int ww = 0; ww < NW; ww++) tot += dyn[ww];
            g_xs2_hat[bn * CC + tid] = xm / fmaxf(sqrtf(tot), 1e-12f);
            __syncthreads();
        }
    }
    gridBar();

    // ===== Phase 2: MLP partials (12 rows x 16 hidden chunks) =====
    for (int task = blockIdx.x; task < (BB + BB*NN) * HCH; task += gridDim.x) {
        int row = task / HCH, ch = task % HCH;
        float* SX = dyn; float* HP = dyn + CC; float* HID = dyn + 2*CC;
        const float *w1, *b1, *w2;
        __syncthreads();
        if (row < BB) {
            w1 = w1t; b1 = b1t; w2 = w2t;
            float s = 0.0f;
#pragma unroll
            for (int n = 0; n < NN; n++)
#pragma unroll
                for (int c2 = 0; c2 < MCH; c2++)
                    s += g_mean_part[((row * NN + n) * MCH + c2) * CC + tid];
            SX[tid] = s * (1.0f / (KT * NN));
        } else {
            int r = row - BB;
            w1 = w1c; b1 = b1c; w2 = w2c;
            float s = 0.0f;
#pragma unroll
            for (int c2 = 0; c2 < MCH; c2++)
                s += g_mean_part[(r * MCH + c2) * CC + tid];
            SX[tid] = s * (1.0f / KT);
        }
        __syncthreads();

        int half = tid / HCW, jj = tid % HCW, j0 = ch * HCW;  // half in 0..3
        float h = 0.0f;
        const float* w1p = w1 + (size_t)(half * HCW) * HH + j0 + jj;
#pragma unroll 4
        for (int c = 0; c < HCW; c++) h += SX[half * HCW + c] * w1p[(size_t)c * HH];
        HP[tid] = h;
        __syncthreads();
        if (tid < HCW)
            HID[tid] = fmaxf(HP[tid] + HP[HCW + tid] + HP[2*HCW + tid] + HP[3*HCW + tid]
                             + b1[j0 + tid], 0.0f);
        __syncthreads();

        float o = 0.0f;
        const float* w2p = w2 + (size_t)j0 * CC + tid;
#pragma unroll 4
        for (int j = 0; j < HCW; j++) o += HID[j] * w2p[(size_t)j * CC];
        g_mlp_part[(size_t)task * CC + tid] = o;
        __syncthreads();
    }
    gridBar();

    // ===== Phase 3: main fused pass + shot map_s pass + MLP finish =====
    for (int task = blockIdx.x; task < BB*NCHK*NQG + BB*NN*SCH + BB + BB*NN; task += gridDim.x) {
        if (task < BB*NCHK*NQG) {
            int b = task / (NCHK * NQG);
            int rem = task % (NCHK * NQG);
            int chunk = rem / NQG, qg = rem % NQG;
            int t0 = chunk * TQ;
            int q0 = b * QQ + qg * QG;
            float* SF  = dyn + OFF_SF;
            float* VV  = dyn + OFF_VV;
            float* NSS = dyn + OFF_NSS;
            float* SIM = dyn + OFF_SIM;
            __syncthreads();
            // stage fshot chunk
            for (int i = tid; i < NN * TQ * (CC/4); i += 384) {
                int c4 = i % (CC/4), row = i / (CC/4);
                int n = row / TQ, t = row % TQ;
                float4 u = *(const float4*)(fshot + (((size_t)(b*NN+n))*KT + t0 + t)*CC + c4*4);
                *(float4*)(SF + row*RSTR + c4*4) = u;
            }
            // reconstruct vv = sigm(mlp_cls)*mlp_task from partials (race-free)
            {
                float ot = b2t[tid];
#pragma unroll
                for (int c2 = 0; c2 < HCH; c2++)
                    ot += g_mlp_part[(size_t)(b * HCH + c2) * CC + tid];
#pragma unroll
                for (int n = 0; n < NN; n++) {
                    float oc = b2c[tid];
#pragma unroll
                    for (int c2 = 0; c2 < HCH; c2++)
                        oc += g_mlp_part[(size_t)((BB + b*NN + n) * HCH + c2) * CC + tid];
                    VV[n * RSTR + tid] = sigm(oc) * ot;
                }
            }
            if (tid < NN * TQ) {
                int n = tid / TQ, t = tid % TQ;
                NSS[tid] = g_ns[(b * NN + n) * KT + t0 + t];
            }
            __syncthreads();

            // Pass A: 4 items per warp, 8 lanes per item, t-major enumeration.
            // Packed f32x2 FMA: 22 FFMA2 per iteration instead of 44 FFMA.
            const int g8 = lane >> 3, l8 = lane & 7;
            for (int base = w * 4; base < QG * TQ; base += NW * 4) {
                int item = base + g8;
                bool valid = item < QG * TQ;
                int it = valid ? item : QG * TQ - 1;
                int trel = it / QG, qi = it % QG;
                const float* fp = fq + ((size_t)(q0 + qi) * TT + t0 + trel) * CC + l8 * 4;
                u64 rp[11];
#pragma unroll
                for (int k = 0; k < 11; k++) rp[k] = 0ull;
#pragma unroll 3
                for (int i = 0; i < 12; i++) {
                    ulonglong2 a = *(const ulonglong2*)(fp + i * 32);
                    ffma2(rp[0], a.x, a.x);
                    ffma2(rp[0], a.y, a.y);
#pragma unroll
                    for (int n = 0; n < NN; n++) {
                        ulonglong2 u = *(const ulonglong2*)(SF + (n * TQ + trel) * RSTR + i * 32 + l8 * 4);
                        ffma2(rp[1 + n], a.x, u.x);
                        ffma2(rp[1 + n], a.y, u.y);
                        ulonglong2 v = *(const ulonglong2*)(VV + n * RSTR + i * 32 + l8 * 4);
                        ffma2(rp[6 + n], a.x, v.x);
                        ffma2(rp[6 + n], a.y, v.y);
                    }
                }
                float r[11];
#pragma unroll
                for (int k = 0; k < 11; k++) r[k] = upsum(rp[k]);
                segRed8<11>(r);
                if (l8 == 0 && valid) {
                    float nq = sqrtf(r[0]);
#pragma unroll
                    for (int n = 0; n < NN; n++) {
                        float den = fmaxf(nq * NSS[n * TQ + trel], 1e-8f);
                        SIM[(qi * NN + n) * TQ + trel] = r[1 + n] / den;
                        g_smq[((size_t)(q0 + qi) * NN + n) * TT + t0 + trel] = sigm(r[6 + n]);
                    }
                }
            }
            __syncthreads();

            if (tid < QG * NN) {
                int qi = tid / NN, n = tid % NN;
                float mm = -3.4e38f;
#pragma unroll
                for (int t = 0; t < TQ; t++)
                    mm = fmaxf(mm, SIM[(qi * NN + n) * TQ + t]);
                g_mx_part[((size_t)chunk * BQ + q0 + qi) * NN + n] = mm;
            }
            __syncthreads();
        } else if (task < BB*NCHK*NQG + BB*NN*SCH) {
            int s2 = task - BB*NCHK*NQG;
            int bn = s2 / SCH, ch = s2 % SCH;
            int b = bn / NN;
            int t0 = ch * 40, t1 = min(KT, t0 + 40);
            float* SVV = dyn; float* PW = dyn + CC;
            __syncthreads();
            {
                float ot = b2t[tid], oc = b2c[tid];
#pragma unroll
                for (int c2 = 0; c2 < HCH; c2++) {
                    ot += g_mlp_part[(size_t)(b * HCH + c2) * CC + tid];
                    oc += g_mlp_part[(size_t)((BB + bn) * HCH + c2) * CC + tid];
                }
                SVV[tid] = sigm(oc) * ot;
            }
            __syncthreads();

            float acc[12];
#pragma unroll
            for (int e = 0; e < 12; e++) acc[e] = 0.0f;
            for (int t = t0 + w; t < t1; t += NW) {
                const float* fp = fshot + ((size_t)bn * KT + t) * CC + 4 * lane;
                float fv[12];
#pragma unroll
                for (int j = 0; j < 3; j++) {
                    float4 u = *(const float4*)(fp + 128 * j);
                    fv[4*j] = u.x; fv[4*j+1] = u.y; fv[4*j+2] = u.z; fv[4*j+3] = u.w;
                }
                float r[1] = {0.0f};
#pragma unroll
                for (int j = 0; j < 3; j++) {
                    float4 u = *(const float4*)(&SVV[128 * j + 4 * lane]);
                    r[0] += fv[4*j]*u.x + fv[4*j+1]*u.y + fv[4*j+2]*u.z + fv[4*j+3]*u.w;
                }
                warpRed<1>(r);
                float ms = sigm(r[0]);
#pragma unroll
                for (int e = 0; e < 12; e++) acc[e] += fv[e] * ms;
            }
#pragma unroll
            for (int e = 0; e < 12; e++) {
                int c = 128 * (e >> 2) + (lane << 2) + (e & 3);
                PW[w * CC + c] = acc[e];
            }
            __syncthreads();
            float s = 0.0f;
#pragma unroll
            for (int ww = 0; ww < NW; ww++) s += PW[ww * CC + tid];
            g_shot_part[(size_t)s2 * CC + tid] = s;
            __syncthreads();
        } else {
            int row = task - BB*NCHK*NQG - BB*NN*SCH;
            float o = (row < BB) ? b2t[tid] : b2c[tid];
#pragma unroll
            for (int c2 = 0; c2 < HCH; c2++) o += g_mlp_part[(size_t)(row * HCH + c2) * CC + tid];
            if (row < BB) g_wt[row * CC + tid] = o;
            else          g_wc[(row - BB) * CC + tid] = sigm(o);
        }
    }
    gridBar();

    // ===== Phase 4: accq from fq re-stream (packed t-pairs) + final outputs =====
    for (int bq = blockIdx.x; bq < BQ; bq += gridDim.x) {
        int b = bq / QQ;
        float* SMQ5 = dyn;                    // NN*TT = 980
        float* CW = dyn + NN*TT;              // NW*21
        float* TOT = CW + NW*21;
        __syncthreads();
        for (int i = tid; i < NN * TT; i += 384)
            SMQ5[i] = g_smq[(size_t)bq * NN * TT + i];
        __syncthreads();

        if (tid == 0) {
            float s = 0.0f;
#pragma unroll
            for (int n = 0; n < NN; n++) {
                float mm = -3.4e38f;
                for (int ch = 0; ch < NCHK; ch++)
                    mm = fmaxf(mm, g_mx_part[((size_t)ch * BQ + bq) * NN + n]);
                s += mm;
            }
            s *= (1.0f / NN);
            out[bq] = s;
            out[BQ + bq] = s;
        }

        // accq[n][c=tid] = sum_t fq[t,c] * smq[n,t]   (t processed in packed pairs)
        u64 accp[NN];
#pragma unroll
        for (int n = 0; n < NN; n++) accp[n] = 0ull;
        const float* fcol = fq + (size_t)bq * TT * CC + tid;
#pragma unroll 4
        for (int t = 0; t < TT; t += 2) {
            float f0 = fcol[(size_t)t * CC];
            float f1 = fcol[(size_t)(t + 1) * CC];
            u64 fp2 = pk2(f0, f1);
#pragma unroll
            for (int n = 0; n < NN; n++)
                ffma2(accp[n], fp2, *(const u64*)(SMQ5 + n * TT + t));
        }
        float acc[NN];
#pragma unroll
        for (int n = 0; n < NN; n++) acc[n] = upsum(accp[n]);

        float xqv = xq_in[(size_t)bq * CC + tid];
        float pv[21];
        pv[0] = xqv * xqv;
#pragma unroll
        for (int n = 0; n < NN; n++) {
            float wcv = g_wc[(b * NN + n) * CC + tid];
            float sp = 0.0f;
#pragma unroll
            for (int ch = 0; ch < SCH; ch++)
                sp += g_shot_part[(size_t)((b * NN + n) * SCH + ch) * CC + tid];
            float xsr = wcv * sp * (1.0f / KT);
            float xqr = wcv * acc[n] * (1.0f / TT);
            pv[1 + n]  = xqv * g_xs2_hat[(b * NN + n) * CC + tid];
            pv[6 + n]  = xqr * xqr;
            pv[11 + n] = xqr * xsr;
            pv[16 + n] = xsr * xsr;
        }
        warpRed<21>(pv);
        if (lane == 0) {
#pragma unroll
            for (int k = 0; k < 21; k++) CW[w * 21 + k] = pv[k];
        }
        __syncthreads();
        if (tid < 21) {
            float s = 0.0f;
#pragma unroll
            for (int ww = 0; ww < NW; ww++) s += CW[ww * 21 + tid];
            TOT[tid] = s;
        }
        __syncthreads();
        if (tid < NN) {
            float nq2 = fmaxf(sqrtf(TOT[0]), 1e-12f);
            out[2 * BQ + bq * NN + tid] = TEMPF * TOT[1 + tid] / nq2;
            out[2 * BQ + BQ * NN + bq * NN + tid] =
                TOT[11 + tid] / ((1e-16f + sqrtf(TOT[6 + tid])) * (1e-16f + sqrtf(TOT[16 + tid])));
        }
        __syncthreads();
    }
}

extern "C" void kernel_launch(void* const* d_in, const int* in_sizes, int n_in,
                              void* d_out, int out_size) {
    const float* feat_shot  = (const float*)d_in[0];
    const float* feat_query = (const float*)d_in[1];
    const float* x_shot     = (const float*)d_in[2];
    const float* x_query    = (const float*)d_in[3];
    const float* w1_task    = (const float*)d_in[4];
    const float* b1_task    = (const float*)d_in[5];
    const float* w2_task    = (const float*)d_in[6];
    const float* b2_task    = (const float*)d_in[7];
    const float* w1_cls     = (const float*)d_in[8];
    const float* b1_cls     = (const float*)d_in[9];
    const float* w2_cls     = (const float*)d_in[10];
    const float* b2_cls     = (const float*)d_in[11];
    float* out = (float*)d_out;

    cudaFuncSetAttribute(kFused, cudaFuncAttributeMaxDynamicSharedMemorySize, DYN_BYTES);

    int dev = 0;
    cudaGetDevice(&dev);
    int sms = 0;
    cudaDeviceGetAttribute(&sms, cudaDevAttrMultiProcessorCount, dev);
    int maxBlk = 1;
    cudaOccupancyMaxActiveBlocksPerMultiprocessor(&maxBlk, kFused, 384, DYN_BYTES);
    if (maxBlk < 1) maxBlk = 1;
    int grid = sms * maxBlk;

    kFused<<<grid, 384, DYN_BYTES>>>(feat_shot, feat_query, x_shot, x_query,
                                     w1_task, b1_task, w2_task, b2_task,
                                     w1_cls, b1_cls, w2_cls, b2_cls, out);
}

// round 11
// speedup vs baseline: 1.8095x; 1.0889x over previous
#include <cuda_runtime.h>
#include <math.h>

#define BB 2
#define QQ 75
#define NN 5
#define KK 1
#define TT 196
#define CC 384
#define HH 1536
#define KT 196
#define BQ 150
#define TEMPF 10.0f

#define MCH 7          // t-chunks for fused mean+ns pass (28 rows)
#define SCH 5          // t-chunks for shot map_s pass (40/36 rows)
#define HCH 16         // hidden chunks for MLP (96 units)
#define HCW 96
#define TQ 7           // t-chunk for main pass
#define NCHK 28        // TT / TQ
#define QG 25          // queries per group
#define NQG 3          // QQ / QG
#define NW 12          // warps per block (384 threads)
#define RSTR 392       // padded row stride (floats) for SF/VV
#define NFIN (BB + BB*NN)   // 12 MLP-finish tasks

// ---- dynamic smem layout (floats) ----
#define OFF_SF   0                         // NN*TQ*RSTR = 13720
#define OFF_VV   (OFF_SF + NN*TQ*RSTR)     // NN*RSTR = 1960
#define OFF_NSS  (OFF_VV + NN*RSTR)        // NN*TQ = 35
#define OFF_SIM  (OFF_NSS + NN*TQ)         // QG*NN*TQ = 875
#define DYN_FLOATS (OFF_SIM + QG*NN*TQ)    // 16590
#define DYN_BYTES  (DYN_FLOATS * 4)

typedef unsigned long long u64;

// ---------------- persistent scratch ----------------
__device__ float g_mean_part[BB*NN*MCH*CC];
__device__ float g_mlp_part[(BB + BB*NN)*HCH*CC];
__device__ float g_wt[BB*CC];
__device__ float g_wc[BB*NN*CC];
__device__ float g_ns[BB*NN*KT];
__device__ float g_shot_part[BB*NN*SCH*CC];
__device__ float g_xs2_hat[BB*NN*CC];
__device__ float g_smq[BQ*NN*TT];
__device__ float g_mx_part[NCHK*BQ*NN];
__device__ unsigned g_bar_cnt;
__device__ unsigned g_bar_gen;
__device__ unsigned g_wcwt_done;

template<int NV>
__device__ __forceinline__ void warpRed(float* v) {
#pragma unroll
    for (int off = 16; off; off >>= 1) {
#pragma unroll
        for (int k = 0; k < NV; k++)
            v[k] += __shfl_xor_sync(0xffffffffu, v[k], off);
    }
}

template<int NV>
__device__ __forceinline__ void segRed8(float* v) {
#pragma unroll
    for (int off = 4; off; off >>= 1) {
#pragma unroll
        for (int k = 0; k < NV; k++)
            v[k] += __shfl_xor_sync(0xffffffffu, v[k], off);
    }
}

__device__ __forceinline__ void ffma2(u64& d, u64 a, u64 b) {
    asm("fma.rn.f32x2 %0, %1, %2, %0;" : "+l"(d) : "l"(a), "l"(b));
}
__device__ __forceinline__ float upsum(u64 v) {
    float lo, hi;
    asm("mov.b64 {%0, %1}, %2;" : "=f"(lo), "=f"(hi) : "l"(v));
    return lo + hi;
}
__device__ __forceinline__ u64 pk2(float a, float b) {
    u64 r;
    asm("mov.b64 %0, {%1, %2};" : "=l"(r) : "f"(a), "f"(b));
    return r;
}

__device__ __forceinline__ float sigm(float x) {
    return 1.0f / (1.0f + __expf(-x));
}

__device__ __forceinline__ void gridBar() {
    __syncthreads();
    if (threadIdx.x == 0) {
        __threadfence();
        unsigned gen = *(volatile unsigned*)&g_bar_gen;
        if (atomicAdd(&g_bar_cnt, 1u) == gridDim.x - 1u) {
            g_bar_cnt = 0u;
            __threadfence();
            atomicAdd(&g_bar_gen, 1u);
        } else {
            while (*(volatile unsigned*)&g_bar_gen == gen) __nanosleep(64);
        }
        __threadfence();
    }
    __syncthreads();
}

// wait until all 12 wt/wc rows are published (phase-3 intra-phase dependency)
__device__ __forceinline__ void waitWcWt(int tid) {
    if (tid == 0) {
        while (*(volatile unsigned*)&g_wcwt_done < (unsigned)NFIN) __nanosleep(32);
    }
    __syncthreads();
}

__global__ __launch_bounds__(384, 2) void kFused(
    const float* __restrict__ fshot, const float* __restrict__ fq,
    const float* __restrict__ x_shot, const float* __restrict__ xq_in,
    const float* __restrict__ w1t, const float* __restrict__ b1t,
    const float* __restrict__ w2t, const float* __restrict__ b2t,
    const float* __restrict__ w1c, const float* __restrict__ b1c,
    const float* __restrict__ w2c, const float* __restrict__ b2c,
    float* __restrict__ out) {
    extern __shared__ float dyn[];
    const int tid = threadIdx.x;
    const int w = tid >> 5, lane = tid & 31;

    // ===== Phase 1: fused mean+ns partials (one fshot pass) + plain prototype =====
    if (blockIdx.x == 0 && tid == 0) g_wcwt_done = 0u;   // reset for phase 3
    for (int task = blockIdx.x; task < BB*NN*MCH + BB*NN; task += gridDim.x) {
        if (task < BB*NN*MCH) {
            int bn = task / MCH, ch = task % MCH;
            int t0 = ch * 28;
            float* PW = dyn;     // NW*CC per-warp partials
            __syncthreads();
            float acc[12];
#pragma unroll
            for (int e = 0; e < 12; e++) acc[e] = 0.0f;
            for (int t = t0 + w; t < t0 + 28; t += NW) {
                const float* fp = fshot + ((size_t)bn * KT + t) * CC + 4 * lane;
                float fv[12];
#pragma unroll
                for (int j = 0; j < 3; j++) {
                    float4 u = *(const float4*)(fp + 128 * j);
                    fv[4*j] = u.x; fv[4*j+1] = u.y; fv[4*j+2] = u.z; fv[4*j+3] = u.w;
                }
                float r[1] = {0.0f};
#pragma unroll
                for (int e = 0; e < 12; e++) r[0] += fv[e] * fv[e];
                warpRed<1>(r);
                if (lane == 0) g_ns[bn * KT + t] = sqrtf(r[0]);
#pragma unroll
                for (int e = 0; e < 12; e++) acc[e] += fv[e];
            }
#pragma unroll
            for (int e = 0; e < 12; e++) {
                int c = 128 * (e >> 2) + (lane << 2) + (e & 3);
                PW[w * CC + c] = acc[e];
            }
            __syncthreads();
            float s = 0.0f;
#pragma unroll
            for (int ww = 0; ww < NW; ww++) s += PW[ww * CC + tid];
            g_mean_part[(bn * MCH + ch) * CC + tid] = s;
            __syncthreads();
        } else {
            int bn = task - BB*NN*MCH;
            __syncthreads();
            float xm = x_shot[(size_t)bn * CC + tid];  // KK=1
            float r[1] = {xm * xm};
            warpRed<1>(r);
            if (lane == 0) dyn[w] = r[0];
            __syncthreads();
            float tot = 0.0f;
#pragma unroll
            for (int ww = 0; ww < NW; ww++) tot += dyn[ww];
            g_xs2_hat[bn * CC + tid] = xm / fmaxf(sqrtf(tot), 1e-12f);
            __syncthreads();
        }
    }
    gridBar();

    // ===== Phase 2: MLP partials (12 rows x 16 hidden chunks) =====
    for (int task = blockIdx.x; task < (BB + BB*NN) * HCH; task += gridDim.x) {
        int row = task / HCH, ch = task % HCH;
        float* SX = dyn; float* HP = dyn + CC; float* HID = dyn + 2*CC;
        const float *w1, *b1, *w2;
        __syncthreads();
        if (row < BB) {
            w1 = w1t; b1 = b1t; w2 = w2t;
            float s = 0.0f;
#pragma unroll
            for (int n = 0; n < NN; n++)
#pragma unroll
                for (int c2 = 0; c2 < MCH; c2++)
                    s += g_mean_part[((row * NN + n) * MCH + c2) * CC + tid];
            SX[tid] = s * (1.0f / (KT * NN));
        } else {
            int r = row - BB;
            w1 = w1c; b1 = b1c; w2 = w2c;
            float s = 0.0f;
#pragma unroll
            for (int c2 = 0; c2 < MCH; c2++)
                s += g_mean_part[(r * MCH + c2) * CC + tid];
            SX[tid] = s * (1.0f / KT);
        }
        __syncthreads();

        int half = tid / HCW, jj = tid % HCW, j0 = ch * HCW;  // half in 0..3
        float h = 0.0f;
        const float* w1p = w1 + (size_t)(half * HCW) * HH + j0 + jj;
#pragma unroll 8
        for (int c = 0; c < HCW; c++) h += SX[half * HCW + c] * w1p[(size_t)c * HH];
        HP[tid] = h;
        __syncthreads();
        if (tid < HCW)
            HID[tid] = fmaxf(HP[tid] + HP[HCW + tid] + HP[2*HCW + tid] + HP[3*HCW + tid]
                             + b1[j0 + tid], 0.0f);
        __syncthreads();

        float o = 0.0f;
        const float* w2p = w2 + (size_t)j0 * CC + tid;
#pragma unroll 8
        for (int j = 0; j < HCW; j++) o += HID[j] * w2p[(size_t)j * CC];
        g_mlp_part[(size_t)task * CC + tid] = o;
        __syncthreads();
    }
    gridBar();

    // ===== Phase 3: MLP finish (first!) + shot map_s + main fused pass =====
    for (int task = blockIdx.x; task < NFIN + BB*NN*SCH + BB*NCHK*NQG; task += gridDim.x) {
        if (task < NFIN) {
            // --- publish wt/wc, then signal ---
            int row = task;
            float o = (row < BB) ? b2t[tid] : b2c[tid];
#pragma unroll
            for (int c2 = 0; c2 < HCH; c2++)
                o += g_mlp_part[(size_t)(row * HCH + c2) * CC + tid];
            if (row < BB) g_wt[row * CC + tid] = o;
            else          g_wc[(row - BB) * CC + tid] = sigm(o);
            __syncthreads();
            if (tid == 0) { __threadfence(); atomicAdd(&g_wcwt_done, 1u); }
        } else if (task < NFIN + BB*NN*SCH) {
            int s2 = task - NFIN;
            int bn = s2 / SCH, ch = s2 % SCH;
            int b = bn / NN;
            int t0 = ch * 40, t1 = min(KT, t0 + 40);
            float* SVV = dyn; float* PW = dyn + CC;
            waitWcWt(tid);
            SVV[tid] = g_wc[bn * CC + tid] * g_wt[b * CC + tid];
            __syncthreads();

            float acc[12];
#pragma unroll
            for (int e = 0; e < 12; e++) acc[e] = 0.0f;
            for (int t = t0 + w; t < t1; t += NW) {
                const float* fp = fshot + ((size_t)bn * KT + t) * CC + 4 * lane;
                float fv[12];
#pragma unroll
                for (int j = 0; j < 3; j++) {
                    float4 u = *(const float4*)(fp + 128 * j);
                    fv[4*j] = u.x; fv[4*j+1] = u.y; fv[4*j+2] = u.z; fv[4*j+3] = u.w;
                }
                float r[1] = {0.0f};
#pragma unroll
                for (int j = 0; j < 3; j++) {
                    float4 u = *(const float4*)(&SVV[128 * j + 4 * lane]);
                    r[0] += fv[4*j]*u.x + fv[4*j+1]*u.y + fv[4*j+2]*u.z + fv[4*j+3]*u.w;
                }
                warpRed<1>(r);
                float ms = sigm(r[0]);
#pragma unroll
                for (int e = 0; e < 12; e++) acc[e] += fv[e] * ms;
            }
#pragma unroll
            for (int e = 0; e < 12; e++) {
                int c = 128 * (e >> 2) + (lane << 2) + (e & 3);
                PW[w * CC + c] = acc[e];
            }
            __syncthreads();
            float s = 0.0f;
#pragma unroll
            for (int ww = 0; ww < NW; ww++) s += PW[ww * CC + tid];
            g_shot_part[(size_t)s2 * CC + tid] = s;
            __syncthreads();
        } else {
            int m = task - NFIN - BB*NN*SCH;
            int b = m / (NCHK * NQG);
            int rem = m % (NCHK * NQG);
            int chunk = rem / NQG, qg = rem % NQG;
            int t0 = chunk * TQ;
            int q0 = b * QQ + qg * QG;
            float* SF  = dyn + OFF_SF;
            float* VV  = dyn + OFF_VV;
            float* NSS = dyn + OFF_NSS;
            float* SIM = dyn + OFF_SIM;
            __syncthreads();
            // stage fshot chunk + nss first (independent of wt/wc)
            for (int i = tid; i < NN * TQ * (CC/4); i += 384) {
                int c4 = i % (CC/4), row = i / (CC/4);
                int n = row / TQ, t = row % TQ;
                float4 u = *(const float4*)(fshot + (((size_t)(b*NN+n))*KT + t0 + t)*CC + c4*4);
                *(float4*)(SF + row*RSTR + c4*4) = u;
            }
            if (tid < NN * TQ) {
                int n = tid / TQ, t = tid % TQ;
                NSS[tid] = g_ns[(b * NN + n) * KT + t0 + t];
            }
            waitWcWt(tid);
            {
                float wtb = g_wt[b * CC + tid];
#pragma unroll
                for (int n = 0; n < NN; n++)
                    VV[n * RSTR + tid] = g_wc[(b * NN + n) * CC + tid] * wtb;
            }
            __syncthreads();

            // Pass A: 4 items per warp, 8 lanes per item, t-major; FFMA2 packed
            const int g8 = lane >> 3, l8 = lane & 7;
            for (int base = w * 4; base < QG * TQ; base += NW * 4) {
                int item = base + g8;
                bool valid = item < QG * TQ;
                int it = valid ? item : QG * TQ - 1;
                int trel = it / QG, qi = it % QG;
                const float* fp = fq + ((size_t)(q0 + qi) * TT + t0 + trel) * CC + l8 * 4;
                u64 rp[11];
#pragma unroll
                for (int k = 0; k < 11; k++) rp[k] = 0ull;
#pragma unroll 4
                for (int i = 0; i < 12; i++) {
                    ulonglong2 a = *(const ulonglong2*)(fp + i * 32);
                    ffma2(rp[0], a.x, a.x);
                    ffma2(rp[0], a.y, a.y);
#pragma unroll
                    for (int n = 0; n < NN; n++) {
                        ulonglong2 u = *(const ulonglong2*)(SF + (n * TQ + trel) * RSTR + i * 32 + l8 * 4);
                        ffma2(rp[1 + n], a.x, u.x);
                        ffma2(rp[1 + n], a.y, u.y);
                        ulonglong2 v = *(const ulonglong2*)(VV + n * RSTR + i * 32 + l8 * 4);
                        ffma2(rp[6 + n], a.x, v.x);
                        ffma2(rp[6 + n], a.y, v.y);
                    }
                }
                float r[11];
#pragma unroll
                for (int k = 0; k < 11; k++) r[k] = upsum(rp[k]);
                segRed8<11>(r);
                if (l8 == 0 && valid) {
                    float nq = sqrtf(r[0]);
#pragma unroll
                    for (int n = 0; n < NN; n++) {
                        float den = fmaxf(nq * NSS[n * TQ + trel], 1e-8f);
                        SIM[(qi * NN + n) * TQ + trel] = r[1 + n] / den;
                        g_smq[((size_t)(q0 + qi) * NN + n) * TT + t0 + trel] = sigm(r[6 + n]);
                    }
                }
            }
            __syncthreads();

            if (tid < QG * NN) {
                int qi = tid / NN, n = tid % NN;
                float mm = -3.4e38f;
#pragma unroll
                for (int t = 0; t < TQ; t++)
                    mm = fmaxf(mm, SIM[(qi * NN + n) * TQ + t]);
                g_mx_part[((size_t)chunk * BQ + q0 + qi) * NN + n] = mm;
            }
            __syncthreads();
        }
    }
    gridBar();

    // ===== Phase 4: accq from fq re-stream (packed t-pairs) + final outputs =====
    for (int bq = blockIdx.x; bq < BQ; bq += gridDim.x) {
        int b = bq / QQ;
        float* SMQ5 = dyn;                    // NN*TT = 980
        float* CW = dyn + NN*TT;              // NW*21
        float* TOT = CW + NW*21;
        __syncthreads();
        for (int i = tid; i < NN * TT; i += 384)
            SMQ5[i] = g_smq[(size_t)bq * NN * TT + i];
        __syncthreads();

        if (tid == 0) {
            float s = 0.0f;
#pragma unroll
            for (int n = 0; n < NN; n++) {
                float mm = -3.4e38f;
                for (int ch = 0; ch < NCHK; ch++)
                    mm = fmaxf(mm, g_mx_part[((size_t)ch * BQ + bq) * NN + n]);
                s += mm;
            }
            s *= (1.0f / NN);
            out[bq] = s;
            out[BQ + bq] = s;
        }

        u64 accp[NN];
#pragma unroll
        for (int n = 0; n < NN; n++) accp[n] = 0ull;
        const float* fcol = fq + (size_t)bq * TT * CC + tid;
#pragma unroll 4
        for (int t = 0; t < TT; t += 2) {
            float f0 = fcol[(size_t)t * CC];
            float f1 = fcol[(size_t)(t + 1) * CC];
            u64 fp2 = pk2(f0, f1);
#pragma unroll
            for (int n = 0; n < NN; n++)
                ffma2(accp[n], fp2, *(const u64*)(SMQ5 + n * TT + t));
        }
        float acc[NN];
#pragma unroll
        for (int n = 0; n < NN; n++) acc[n] = upsum(accp[n]);

        float xqv = xq_in[(size_t)bq * CC + tid];
        float pv[21];
        pv[0] = xqv * xqv;
#pragma unroll
        for (int n = 0; n < NN; n++) {
            float wcv = g_wc[(b * NN + n) * CC + tid];
            float sp = 0.0f;
#pragma unroll
            for (int ch = 0; ch < SCH; ch++)
                sp += g_shot_part[(size_t)((b * NN + n) * SCH + ch) * CC + tid];
            float xsr = wcv * sp * (1.0f / KT);
            float xqr = wcv * acc[n] * (1.0f / TT);
            pv[1 + n]  = xqv * g_xs2_hat[(b * NN + n) * CC + tid];
            pv[6 + n]  = xqr * xqr;
            pv[11 + n] = xqr * xsr;
            pv[16 + n] = xsr * xsr;
        }
        warpRed<21>(pv);
        if (lane == 0) {
#pragma unroll
            for (int k = 0; k < 21; k++) CW[w * 21 + k] = pv[k];
        }
        __syncthreads();
        if (tid < 21) {
            float s = 0.0f;
#pragma unroll
            for (int ww = 0; ww < NW; ww++) s += CW[ww * 21 + tid];
            TOT[tid] = s;
        }
        __syncthreads();
        if (tid < NN) {
            float nq2 = fmaxf(sqrtf(TOT[0]), 1e-12f);
            out[2 * BQ + bq * NN + tid] = TEMPF * TOT[1 + tid] / nq2;
            out[2 * BQ + BQ * NN + bq * NN + tid] =
                TOT[11 + tid] / ((1e-16f + sqrtf(TOT[6 + tid])) * (1e-16f + sqrtf(TOT[16 + tid])));
        }
        __syncthreads();
    }
}

extern "C" void kernel_launch(void* const* d_in, const int* in_sizes, int n_in,
                              void* d_out, int out_size) {
    const float* feat_shot  = (const float*)d_in[0];
    const float* feat_query = (const float*)d_in[1];
    const float* x_shot     = (const float*)d_in[2];
    const float* x_query    = (const float*)d_in[3];
    const float* w1_task    = (const float*)d_in[4];
    const float* b1_task    = (const float*)d_in[5];
    const float* w2_task    = (const float*)d_in[6];
    const float* b2_task    = (const float*)d_in[7];
    const float* w1_cls     = (const float*)d_in[8];
    const float* b1_cls     = (const float*)d_in[9];
    const float* w2_cls     = (const float*)d_in[10];
    const float* b2_cls     = (const float*)d_in[11];
    float* out = (float*)d_out;

    cudaFuncSetAttribute(kFused, cudaFuncAttributeMaxDynamicSharedMemorySize, DYN_BYTES);

    int dev = 0;
    cudaGetDevice(&dev);
    int sms = 0;
    cudaDeviceGetAttribute(&sms, cudaDevAttrMultiProcessorCount, dev);
    int maxBlk = 1;
    cudaOccupancyMaxActiveBlocksPerMultiprocessor(&maxBlk, kFused, 384, DYN_BYTES);
    if (maxBlk < 1) maxBlk = 1;
    int grid = sms * maxBlk;

    kFused<<<grid, 384, DYN_BYTES>>>(feat_shot, feat_query, x_shot, x_query,
                                     w1_task, b1_task, w2_task, b2_task,
                                     w1_cls, b1_cls, w2_cls, b2_cls, out);
}

// round 12
// speedup vs baseline: 1.9025x; 1.0514x over previous
#include <cuda_runtime.h>
#include <math.h>

#define BB 2
#define QQ 75
#define NN 5
#define KK 1
#define TT 196
#define CC 384
#define HH 1536
#define KT 196
#define BQ 150
#define TEMPF 10.0f

#define MCH 7          // t-chunks for fused mean+ns pass (28 rows)
#define SCH 5          // t-chunks for shot map_s pass (40/36 rows)
#define HCH 16         // hidden chunks for MLP (96 units)
#define HCW 96
#define TQ 7           // t-chunk for main pass
#define NCHK 28        // TT / TQ
#define QG 25          // queries per group
#define NQG 3          // QQ / QG
#define NW 12          // warps per block (384 threads)
#define RSTR 392       // padded row stride (floats) for SF/VV
#define NFIN (BB + BB*NN)   // 12 MLP-finish tasks

// ---- dynamic smem layout (floats) ----
#define OFF_SF   0                         // NN*TQ*RSTR = 13720
#define OFF_VV   (OFF_SF + NN*TQ*RSTR)     // NN*RSTR = 1960
#define OFF_NSS  (OFF_VV + NN*RSTR)        // NN*TQ = 35
#define OFF_SIM  (OFF_NSS + NN*TQ)         // QG*NN*TQ = 875
#define DYN_FLOATS (OFF_SIM + QG*NN*TQ)    // 16590
#define DYN_BYTES  (DYN_FLOATS * 4)

typedef unsigned long long u64;

// ---------------- persistent scratch ----------------
__device__ float g_mean_part[BB*NN*MCH*CC];
__device__ float g_mlp_part[(BB + BB*NN)*HCH*CC];
__device__ float g_wt[BB*CC];
__device__ float g_wc[BB*NN*CC];
__device__ float g_ns[BB*NN*KT];
__device__ float g_shot_part[BB*NN*SCH*CC];
__device__ float g_xs2_hat[BB*NN*CC];
__device__ float g_smq[BQ*NN*TT];
__device__ float g_mx_part[NCHK*BQ*NN];
__device__ unsigned g_bar_cnt;
__device__ unsigned g_bar_gen;
__device__ unsigned g_wcwt_done;

template<int NV>
__device__ __forceinline__ void warpRed(float* v) {
#pragma unroll
    for (int off = 16; off; off >>= 1) {
#pragma unroll
        for (int k = 0; k < NV; k++)
            v[k] += __shfl_xor_sync(0xffffffffu, v[k], off);
    }
}

template<int NV>
__device__ __forceinline__ void segRed8(float* v) {
#pragma unroll
    for (int off = 4; off; off >>= 1) {
#pragma unroll
        for (int k = 0; k < NV; k++)
            v[k] += __shfl_xor_sync(0xffffffffu, v[k], off);
    }
}

__device__ __forceinline__ void ffma2(u64& d, u64 a, u64 b) {
    asm("fma.rn.f32x2 %0, %1, %2, %0;" : "+l"(d) : "l"(a), "l"(b));
}
__device__ __forceinline__ float upsum(u64 v) {
    float lo, hi;
    asm("mov.b64 {%0, %1}, %2;" : "=f"(lo), "=f"(hi) : "l"(v));
    return lo + hi;
}
__device__ __forceinline__ void unpk2(u64 v, float& lo, float& hi) {
    asm("mov.b64 {%0, %1}, %2;" : "=f"(lo), "=f"(hi) : "l"(v));
}
__device__ __forceinline__ u64 pk2(float a, float b) {
    u64 r;
    asm("mov.b64 %0, {%1, %2};" : "=l"(r) : "f"(a), "f"(b));
    return r;
}

__device__ __forceinline__ float sigm(float x) {
    return 1.0f / (1.0f + __expf(-x));
}

__device__ __forceinline__ void gridBar() {
    __syncthreads();
    if (threadIdx.x == 0) {
        __threadfence();
        unsigned gen = *(volatile unsigned*)&g_bar_gen;
        if (atomicAdd(&g_bar_cnt, 1u) == gridDim.x - 1u) {
            g_bar_cnt = 0u;
            __threadfence();
            atomicAdd(&g_bar_gen, 1u);
        } else {
            while (*(volatile unsigned*)&g_bar_gen == gen) __nanosleep(64);
        }
        __threadfence();
    }
    __syncthreads();
}

__device__ __forceinline__ void waitWcWt(int tid) {
    if (tid == 0) {
        while (*(volatile unsigned*)&g_wcwt_done < (unsigned)NFIN) __nanosleep(32);
    }
    __syncthreads();
}

__global__ __launch_bounds__(384, 2) void kFused(
    const float* __restrict__ fshot, const float* __restrict__ fq,
    const float* __restrict__ x_shot, const float* __restrict__ xq_in,
    const float* __restrict__ w1t, const float* __restrict__ b1t,
    const float* __restrict__ w2t, const float* __restrict__ b2t,
    const float* __restrict__ w1c, const float* __restrict__ b1c,
    const float* __restrict__ w2c, const float* __restrict__ b2c,
    float* __restrict__ out) {
    extern __shared__ float dyn[];
    const int tid = threadIdx.x;
    const int w = tid >> 5, lane = tid & 31;

    // ===== Phase 1: fused mean+ns partials (one fshot pass) + plain prototype =====
    if (blockIdx.x == 0 && tid == 0) g_wcwt_done = 0u;   // reset for phase 3
    for (int task = blockIdx.x; task < BB*NN*MCH + BB*NN; task += gridDim.x) {
        if (task < BB*NN*MCH) {
            int bn = task / MCH, ch = task % MCH;
            int t0 = ch * 28;
            float* PW = dyn;     // NW*CC per-warp partials
            __syncthreads();
            float acc[12];
#pragma unroll
            for (int e = 0; e < 12; e++) acc[e] = 0.0f;
            for (int t = t0 + w; t < t0 + 28; t += NW) {
                const float* fp = fshot + ((size_t)bn * KT + t) * CC + 4 * lane;
                float fv[12];
#pragma unroll
                for (int j = 0; j < 3; j++) {
                    float4 u = *(const float4*)(fp + 128 * j);
                    fv[4*j] = u.x; fv[4*j+1] = u.y; fv[4*j+2] = u.z; fv[4*j+3] = u.w;
                }
                float r[1] = {0.0f};
#pragma unroll
                for (int e = 0; e < 12; e++) r[0] += fv[e] * fv[e];
                warpRed<1>(r);
                if (lane == 0) g_ns[bn * KT + t] = sqrtf(r[0]);
#pragma unroll
                for (int e = 0; e < 12; e++) acc[e] += fv[e];
            }
#pragma unroll
            for (int e = 0; e < 12; e++) {
                int c = 128 * (e >> 2) + (lane << 2) + (e & 3);
                PW[w * CC + c] = acc[e];
            }
            __syncthreads();
            float s = 0.0f;
#pragma unroll
            for (int ww = 0; ww < NW; ww++) s += PW[ww * CC + tid];
            g_mean_part[(bn * MCH + ch) * CC + tid] = s;
            __syncthreads();
        } else {
            int bn = task - BB*NN*MCH;
            __syncthreads();
            float xm = x_shot[(size_t)bn * CC + tid];  // KK=1
            float r[1] = {xm * xm};
            warpRed<1>(r);
            if (lane == 0) dyn[w] = r[0];
            __syncthreads();
            float tot = 0.0f;
#pragma unroll
            for (int ww = 0; ww < NW; ww++) tot += dyn[ww];
            g_xs2_hat[bn * CC + tid] = xm / fmaxf(sqrtf(tot), 1e-12f);
            __syncthreads();
        }
    }
    gridBar();

    // ===== Phase 2: MLP partials (12 rows x 16 hidden chunks), float2 w1 =====
    for (int task = blockIdx.x; task < (BB + BB*NN) * HCH; task += gridDim.x) {
        int row = task / HCH, ch = task % HCH;
        float* SX = dyn; float* HP = dyn + CC; float* HID = dyn + CC + 8*HCW;
        const float *w1, *b1, *w2;
        __syncthreads();
        if (row < BB) {
            w1 = w1t; b1 = b1t; w2 = w2t;
            float s = 0.0f;
#pragma unroll
            for (int n = 0; n < NN; n++)
#pragma unroll
                for (int c2 = 0; c2 < MCH; c2++)
                    s += g_mean_part[((row * NN + n) * MCH + c2) * CC + tid];
            SX[tid] = s * (1.0f / (KT * NN));
        } else {
            int r = row - BB;
            w1 = w1c; b1 = b1c; w2 = w2c;
            float s = 0.0f;
#pragma unroll
            for (int c2 = 0; c2 < MCH; c2++)
                s += g_mean_part[(r * MCH + c2) * CC + tid];
            SX[tid] = s * (1.0f / KT);
        }
        __syncthreads();

        // thread = (ce = c-eighth 0..7, jp = j-pair 0..47); float2 w1 loads
        int ce = tid / 48, jp = tid % 48, j0 = ch * HCW;
        u64 hp2 = 0ull;
        const float* w1b = w1 + j0 + jp * 2;
#pragma unroll 8
        for (int c = 0; c < 48; c++) {
            float x = SX[ce * 48 + c];
            u64 wv = *(const u64*)(w1b + (size_t)(ce * 48 + c) * HH);
            ffma2(hp2, pk2(x, x), wv);
        }
        {
            float h0, h1;
            unpk2(hp2, h0, h1);
            HP[ce * HCW + jp * 2]     = h0;
            HP[ce * HCW + jp * 2 + 1] = h1;
        }
        __syncthreads();
        if (tid < HCW) {
            float s = b1[j0 + tid];
#pragma unroll
            for (int e = 0; e < 8; e++) s += HP[e * HCW + tid];
            HID[tid] = fmaxf(s, 0.0f);
        }
        __syncthreads();

        float o = 0.0f;
        const float* w2p = w2 + (size_t)j0 * CC + tid;
#pragma unroll 8
        for (int j = 0; j < HCW; j++) o += HID[j] * w2p[(size_t)j * CC];
        g_mlp_part[(size_t)task * CC + tid] = o;
        __syncthreads();
    }
    gridBar();

    // ===== Phase 3: MLP finish (first!) + shot map_s + main fused pass =====
    for (int task = blockIdx.x; task < NFIN + BB*NN*SCH + BB*NCHK*NQG; task += gridDim.x) {
        if (task < NFIN) {
            int row = task;
            float o = (row < BB) ? b2t[tid] : b2c[tid];
#pragma unroll
            for (int c2 = 0; c2 < HCH; c2++)
                o += g_mlp_part[(size_t)(row * HCH + c2) * CC + tid];
            if (row < BB) g_wt[row * CC + tid] = o;
            else          g_wc[(row - BB) * CC + tid] = sigm(o);
            __syncthreads();
            if (tid == 0) { __threadfence(); atomicAdd(&g_wcwt_done, 1u); }
        } else if (task < NFIN + BB*NN*SCH) {
            int s2 = task - NFIN;
            int bn = s2 / SCH, ch = s2 % SCH;
            int b = bn / NN;
            int t0 = ch * 40, t1 = min(KT, t0 + 40);
            float* SVV = dyn; float* PW = dyn + CC;
            waitWcWt(tid);
            SVV[tid] = g_wc[bn * CC + tid] * g_wt[b * CC + tid];
            __syncthreads();

            float acc[12];
#pragma unroll
            for (int e = 0; e < 12; e++) acc[e] = 0.0f;
            for (int t = t0 + w; t < t1; t += NW) {
                const float* fp = fshot + ((size_t)bn * KT + t) * CC + 4 * lane;
                float fv[12];
#pragma unroll
                for (int j = 0; j < 3; j++) {
                    float4 u = *(const float4*)(fp + 128 * j);
                    fv[4*j] = u.x; fv[4*j+1] = u.y; fv[4*j+2] = u.z; fv[4*j+3] = u.w;
                }
                float r[1] = {0.0f};
#pragma unroll
                for (int j = 0; j < 3; j++) {
                    float4 u = *(const float4*)(&SVV[128 * j + 4 * lane]);
                    r[0] += fv[4*j]*u.x + fv[4*j+1]*u.y + fv[4*j+2]*u.z + fv[4*j+3]*u.w;
                }
                warpRed<1>(r);
                float ms = sigm(r[0]);
#pragma unroll
                for (int e = 0; e < 12; e++) acc[e] += fv[e] * ms;
            }
#pragma unroll
            for (int e = 0; e < 12; e++) {
                int c = 128 * (e >> 2) + (lane << 2) + (e & 3);
                PW[w * CC + c] = acc[e];
            }
            __syncthreads();
            float s = 0.0f;
#pragma unroll
            for (int ww = 0; ww < NW; ww++) s += PW[ww * CC + tid];
            g_shot_part[(size_t)s2 * CC + tid] = s;
            __syncthreads();
        } else {
            int m = task - NFIN - BB*NN*SCH;
            int b = m / (NCHK * NQG);
            int rem = m % (NCHK * NQG);
            int chunk = rem / NQG, qg = rem % NQG;
            int t0 = chunk * TQ;
            int q0 = b * QQ + qg * QG;
            float* SF  = dyn + OFF_SF;
            float* VV  = dyn + OFF_VV;
            float* NSS = dyn + OFF_NSS;
            float* SIM = dyn + OFF_SIM;
            __syncthreads();
            for (int i = tid; i < NN * TQ * (CC/4); i += 384) {
                int c4 = i % (CC/4), row = i / (CC/4);
                int n = row / TQ, t = row % TQ;
                float4 u = *(const float4*)(fshot + (((size_t)(b*NN+n))*KT + t0 + t)*CC + c4*4);
                *(float4*)(SF + row*RSTR + c4*4) = u;
            }
            if (tid < NN * TQ) {
                int n = tid / TQ, t = tid % TQ;
                NSS[tid] = g_ns[(b * NN + n) * KT + t0 + t];
            }
            waitWcWt(tid);
            {
                float wtb = g_wt[b * CC + tid];
#pragma unroll
                for (int n = 0; n < NN; n++)
                    VV[n * RSTR + tid] = g_wc[(b * NN + n) * CC + tid] * wtb;
            }
            __syncthreads();

            const int g8 = lane >> 3, l8 = lane & 7;
            for (int base = w * 4; base < QG * TQ; base += NW * 4) {
                int item = base + g8;
                bool valid = item < QG * TQ;
                int it = valid ? item : QG * TQ - 1;
                int trel = it / QG, qi = it % QG;
                const float* fp = fq + ((size_t)(q0 + qi) * TT + t0 + trel) * CC + l8 * 4;
                u64 rp[11];
#pragma unroll
                for (int k = 0; k < 11; k++) rp[k] = 0ull;
#pragma unroll 4
                for (int i = 0; i < 12; i++) {
                    ulonglong2 a = *(const ulonglong2*)(fp + i * 32);
                    ffma2(rp[0], a.x, a.x);
                    ffma2(rp[0], a.y, a.y);
#pragma unroll
                    for (int n = 0; n < NN; n++) {
                        ulonglong2 u = *(const ulonglong2*)(SF + (n * TQ + trel) * RSTR + i * 32 + l8 * 4);
                        ffma2(rp[1 + n], a.x, u.x);
                        ffma2(rp[1 + n], a.y, u.y);
                        ulonglong2 v = *(const ulonglong2*)(VV + n * RSTR + i * 32 + l8 * 4);
                        ffma2(rp[6 + n], a.x, v.x);
                        ffma2(rp[6 + n], a.y, v.y);
                    }
                }
                float r[11];
#pragma unroll
                for (int k = 0; k < 11; k++) r[k] = upsum(rp[k]);
                segRed8<11>(r);
                if (l8 == 0 && valid) {
                    float nq = sqrtf(r[0]);
#pragma unroll
                    for (int n = 0; n < NN; n++) {
                        float den = fmaxf(nq * NSS[n * TQ + trel], 1e-8f);
                        SIM[(qi * NN + n) * TQ + trel] = r[1 + n] / den;
                        g_smq[((size_t)(q0 + qi) * NN + n) * TT + t0 + trel] = sigm(r[6 + n]);
                    }
                }
            }
            __syncthreads();

            if (tid < QG * NN) {
                int qi = tid / NN, n = tid % NN;
                float mm = -3.4e38f;
#pragma unroll
                for (int t = 0; t < TQ; t++)
                    mm = fmaxf(mm, SIM[(qi * NN + n) * TQ + t]);
                g_mx_part[((size_t)chunk * BQ + q0 + qi) * NN + n] = mm;
            }
            __syncthreads();
        }
    }
    gridBar();

    // ===== Phase 4: accq via 4-way t-split + float4 fq loads + finals =====
    for (int bq = blockIdx.x; bq < BQ; bq += gridDim.x) {
        int b = bq / QQ;
        float* SMQ5 = dyn;                      // NN*TT = 980
        float* PW4  = dyn + NN*TT;              // 4*NN*CC = 7680
        float* CW   = PW4 + 4*NN*CC;            // NW*21
        float* TOT  = CW + NW*21;
        __syncthreads();
        for (int i = tid; i < NN * TT; i += 384)
            SMQ5[i] = g_smq[(size_t)bq * NN * TT + i];
        __syncthreads();

        if (tid == 0) {
            float s = 0.0f;
#pragma unroll
            for (int n = 0; n < NN; n++) {
                float mm = -3.4e38f;
                for (int ch = 0; ch < NCHK; ch++)
                    mm = fmaxf(mm, g_mx_part[((size_t)ch * BQ + bq) * NN + n]);
                s += mm;
            }
            s *= (1.0f / NN);
            out[bq] = s;
            out[BQ + bq] = s;
        }

        // thread = (tq = t-quarter 0..3, c4 = channel-quad 0..95)
        {
            int tq = tid / 96, c4 = tid % 96;
            u64 accp[NN][2];
#pragma unroll
            for (int n = 0; n < NN; n++) { accp[n][0] = 0ull; accp[n][1] = 0ull; }
            const float* fp4 = fq + ((size_t)bq * TT + tq * 49) * CC + c4 * 4;
#pragma unroll 7
            for (int t = 0; t < 49; t++) {
                ulonglong2 a = *(const ulonglong2*)(fp4 + (size_t)t * CC);
#pragma unroll
                for (int n = 0; n < NN; n++) {
                    float s = SMQ5[n * TT + tq * 49 + t];
                    u64 ss = pk2(s, s);
                    ffma2(accp[n][0], a.x, ss);
                    ffma2(accp[n][1], a.y, ss);
                }
            }
#pragma unroll
            for (int n = 0; n < NN; n++) {
                float l0, h0, l1, h1;
                unpk2(accp[n][0], l0, h0);
                unpk2(accp[n][1], l1, h1);
                float* p = PW4 + (tq * NN + n) * CC + c4 * 4;
                p[0] = l0; p[1] = h0; p[2] = l1; p[3] = h1;
            }
        }
        __syncthreads();

        float acc[NN];
#pragma unroll
        for (int n = 0; n < NN; n++) {
            float s = 0.0f;
#pragma unroll
            for (int q2 = 0; q2 < 4; q2++) s += PW4[(q2 * NN + n) * CC + tid];
            acc[n] = s;
        }

        float xqv = xq_in[(size_t)bq * CC + tid];
        float pv[21];
        pv[0] = xqv * xqv;
#pragma unroll
        for (int n = 0; n < NN; n++) {
            float wcv = g_wc[(b * NN + n) * CC + tid];
            float sp = 0.0f;
#pragma unroll
            for (int ch = 0; ch < SCH; ch++)
                sp += g_shot_part[(size_t)((b * NN + n) * SCH + ch) * CC + tid];
            float xsr = wcv * sp * (1.0f / KT);
            float xqr = wcv * acc[n] * (1.0f / TT);
            pv[1 + n]  = xqv * g_xs2_hat[(b * NN + n) * CC + tid];
            pv[6 + n]  = xqr * xqr;
            pv[11 + n] = xqr * xsr;
            pv[16 + n] = xsr * xsr;
        }
        warpRed<21>(pv);
        if (lane == 0) {
#pragma unroll
            for (int k = 0; k < 21; k++) CW[w * 21 + k] = pv[k];
        }
        __syncthreads();
        if (tid < 21) {
            float s = 0.0f;
#pragma unroll
            for (int ww = 0; ww < NW; ww++) s += CW[ww * 21 + tid];
            TOT[tid] = s;
        }
        __syncthreads();
        if (tid < NN) {
            float nq2 = fmaxf(sqrtf(TOT[0]), 1e-12f);
            out[2 * BQ + bq * NN + tid] = TEMPF * TOT[1 + tid] / nq2;
            out[2 * BQ + BQ * NN + bq * NN + tid] =
                TOT[11 + tid] / ((1e-16f + sqrtf(TOT[6 + tid])) * (1e-16f + sqrtf(TOT[16 + tid])));
        }
        __syncthreads();
    }
}

extern "C" void kernel_launch(void* const* d_in, const int* in_sizes, int n_in,
                              void* d_out, int out_size) {
    const float* feat_shot  = (const float*)d_in[0];
    const float* feat_query = (const float*)d_in[1];
    const float* x_shot     = (const float*)d_in[2];
    const float* x_query    = (const float*)d_in[3];
    const float* w1_task    = (const float*)d_in[4];
    const float* b1_task    = (const float*)d_in[5];
    const float* w2_task    = (const float*)d_in[6];
    const float* b2_task    = (const float*)d_in[7];
    const float* w1_cls     = (const float*)d_in[8];
    const float* b1_cls     = (const float*)d_in[9];
    const float* w2_cls     = (const float*)d_in[10];
    const float* b2_cls     = (const float*)d_in[11];
    float* out = (float*)d_out;

    cudaFuncSetAttribute(kFused, cudaFuncAttributeMaxDynamicSharedMemorySize, DYN_BYTES);

    int dev = 0;
    cudaGetDevice(&dev);
    int sms = 0;
    cudaDeviceGetAttribute(&sms, cudaDevAttrMultiProcessorCount, dev);
    int maxBlk = 1;
    cudaOccupancyMaxActiveBlocksPerMultiprocessor(&maxBlk, kFused, 384, DYN_BYTES);
    if (maxBlk < 1) maxBlk = 1;
    int grid = sms * maxBlk;

    kFused<<<grid, 384, DYN_BYTES>>>(feat_shot, feat_query, x_shot, x_query,
                                     w1_task, b1_task, w2_task, b2_task,
                                     w1_cls, b1_cls, w2_cls, b2_cls, out);
}

// round 13
// speedup vs baseline: 2.0322x; 1.0681x over previous
#include <cuda_runtime.h>
#include <math.h>

#define BB 2
#define QQ 75
#define NN 5
#define KK 1
#define TT 196
#define CC 384
#define HH 1536
#define KT 196
#define BQ 150
#define TEMPF 10.0f

#define MCH 7          // t-chunks for fused mean+ns pass (28 rows)
#define SCH 5          // t-chunks for shot map_s pass (40/36 rows)
#define HCH 16         // hidden chunks for MLP (96 units)
#define HCW 96
#define TQ 7           // t-chunk for main pass
#define NCHK 28        // TT / TQ
#define QG 25          // queries per group
#define NQG 3          // QQ / QG
#define NW 12          // warps per block (384 threads)
#define RSTR 392       // padded row stride (floats) for SF/VV
#define NFIN (BB + BB*NN)   // 12 MLP-finish tasks

// ---- task stream layout ----
#define T0N (BB*NN*MCH)            // 70  mean+ns
#define T1N (BB*NN)                // 10  xs2_hat
#define T2N ((BB + BB*NN)*HCH)     // 192 MLP partials
#define T3N NFIN                   // 12  MLP finish
#define T4N (BB*NN*SCH)            // 50  shot map_s
#define T5N (BB*NCHK*NQG)          // 168 main pass
#define T6N BQ                     // 150 finals
#define T0E T0N
#define T1E (T0E + T1N)
#define T2E (T1E + T2N)
#define T3E (T2E + T3N)
#define T4E (T3E + T4N)
#define T5E (T4E + T5N)
#define T6E (T5E + T6N)            // 652
#define SHOT_TGT (T4N + T1N)       // 60 (xs2 folded in)

// ---- dynamic smem layout (floats) ----
#define OFF_SF   0                         // NN*TQ*RSTR = 13720
#define OFF_VV   (OFF_SF + NN*TQ*RSTR)     // NN*RSTR = 1960
#define OFF_NSS  (OFF_VV + NN*RSTR)        // NN*TQ = 35
#define OFF_SIM  (OFF_NSS + NN*TQ)         // QG*NN*TQ = 875
#define DYN_FLOATS (OFF_SIM + QG*NN*TQ)    // 16590
#define DYN_BYTES  (DYN_FLOATS * 4)

typedef unsigned long long u64;

// ---------------- persistent scratch ----------------
__device__ float g_mean_part[BB*NN*MCH*CC];
__device__ float g_mlp_part[(BB + BB*NN)*HCH*CC];
__device__ float g_wt[BB*CC];
__device__ float g_wc[BB*NN*CC];
__device__ float g_ns[BB*NN*KT];
__device__ float g_shot_part[BB*NN*SCH*CC];
__device__ float g_xs2_hat[BB*NN*CC];
__device__ float g_smq[BQ*NN*TT];
__device__ float g_mx_part[NCHK*BQ*NN];
__device__ unsigned g_bar_cnt;
__device__ unsigned g_bar_gen;
__device__ unsigned g_mean_done;    // -> 70   (reset at kernel end)
__device__ unsigned g_mlp_done;     // -> 192
__device__ unsigned g_wcwt_done;    // -> 12
__device__ unsigned g_shot_done;    // -> 60
__device__ unsigned g_bq_done[BQ];  // -> 28 each

template<int NV>
__device__ __forceinline__ void warpRed(float* v) {
#pragma unroll
    for (int off = 16; off; off >>= 1) {
#pragma unroll
        for (int k = 0; k < NV; k++)
            v[k] += __shfl_xor_sync(0xffffffffu, v[k], off);
    }
}

template<int NV>
__device__ __forceinline__ void segRed8(float* v) {
#pragma unroll
    for (int off = 4; off; off >>= 1) {
#pragma unroll
        for (int k = 0; k < NV; k++)
            v[k] += __shfl_xor_sync(0xffffffffu, v[k], off);
    }
}

__device__ __forceinline__ void ffma2(u64& d, u64 a, u64 b) {
    asm("fma.rn.f32x2 %0, %1, %2, %0;" : "+l"(d) : "l"(a), "l"(b));
}
__device__ __forceinline__ float upsum(u64 v) {
    float lo, hi;
    asm("mov.b64 {%0, %1}, %2;" : "=f"(lo), "=f"(hi) : "l"(v));
    return lo + hi;
}
__device__ __forceinline__ void unpk2(u64 v, float& lo, float& hi) {
    asm("mov.b64 {%0, %1}, %2;" : "=f"(lo), "=f"(hi) : "l"(v));
}
__device__ __forceinline__ u64 pk2(float a, float b) {
    u64 r;
    asm("mov.b64 %0, {%1, %2};" : "=l"(r) : "f"(a), "f"(b));
    return r;
}

__device__ __forceinline__ float sigm(float x) {
    return 1.0f / (1.0f + __expf(-x));
}

__device__ __forceinline__ void gridBar() {
    __syncthreads();
    if (threadIdx.x == 0) {
        __threadfence();
        unsigned gen = *(volatile unsigned*)&g_bar_gen;
        if (atomicAdd(&g_bar_cnt, 1u) == gridDim.x - 1u) {
            g_bar_cnt = 0u;
            __threadfence();
            atomicAdd(&g_bar_gen, 1u);
        } else {
            while (*(volatile unsigned*)&g_bar_gen == gen) __nanosleep(64);
        }
        __threadfence();
    }
    __syncthreads();
}

// consumer: block-wide wait until counter reaches target
__device__ __forceinline__ void waitCnt(unsigned* c, unsigned target) {
    if (threadIdx.x == 0) {
        while (*(volatile unsigned*)c < target) __nanosleep(32);
    }
    __syncthreads();
}

// producer: publish prior global writes, then bump counter
__device__ __forceinline__ void signalCnt(unsigned* c) {
    __threadfence();
    __syncthreads();
    if (threadIdx.x == 0) atomicAdd(c, 1u);
}

__global__ __launch_bounds__(384, 2) void kFused(
    const float* __restrict__ fshot, const float* __restrict__ fq,
    const float* __restrict__ x_shot, const float* __restrict__ xq_in,
    const float* __restrict__ w1t, const float* __restrict__ b1t,
    const float* __restrict__ w2t, const float* __restrict__ b2t,
    const float* __restrict__ w1c, const float* __restrict__ b1c,
    const float* __restrict__ w2c, const float* __restrict__ b2c,
    float* __restrict__ out) {
    extern __shared__ float dyn[];
    const int tid = threadIdx.x;
    const int w = tid >> 5, lane = tid & 31;

    for (int task = blockIdx.x; task < T6E; task += gridDim.x) {
        __syncthreads();   // protect dyn reuse between tasks
        if (task < T0E) {
            // ===== T0: fused mean + ns partials =====
            int bn = task / MCH, ch = task % MCH;
            int t0 = ch * 28;
            float* PW = dyn;
            float acc[12];
#pragma unroll
            for (int e = 0; e < 12; e++) acc[e] = 0.0f;
            for (int t = t0 + w; t < t0 + 28; t += NW) {
                const float* fp = fshot + ((size_t)bn * KT + t) * CC + 4 * lane;
                float fv[12];
#pragma unroll
                for (int j = 0; j < 3; j++) {
                    float4 u = *(const float4*)(fp + 128 * j);
                    fv[4*j] = u.x; fv[4*j+1] = u.y; fv[4*j+2] = u.z; fv[4*j+3] = u.w;
                }
                float r[1] = {0.0f};
#pragma unroll
                for (int e = 0; e < 12; e++) r[0] += fv[e] * fv[e];
                warpRed<1>(r);
                if (lane == 0) g_ns[bn * KT + t] = sqrtf(r[0]);
#pragma unroll
                for (int e = 0; e < 12; e++) acc[e] += fv[e];
            }
#pragma unroll
            for (int e = 0; e < 12; e++) {
                int c = 128 * (e >> 2) + (lane << 2) + (e & 3);
                PW[w * CC + c] = acc[e];
            }
            __syncthreads();
            float s = 0.0f;
#pragma unroll
            for (int ww = 0; ww < NW; ww++) s += PW[ww * CC + tid];
            g_mean_part[(bn * MCH + ch) * CC + tid] = s;
            signalCnt(&g_mean_done);
        } else if (task < T1E) {
            // ===== T1: plain prototype (counts toward shot_done) =====
            int bn = task - T0E;
            float xm = x_shot[(size_t)bn * CC + tid];  // KK=1
            float r[1] = {xm * xm};
            warpRed<1>(r);
            if (lane == 0) dyn[w] = r[0];
            __syncthreads();
            float tot = 0.0f;
#pragma unroll
            for (int ww = 0; ww < NW; ww++) tot += dyn[ww];
            g_xs2_hat[bn * CC + tid] = xm / fmaxf(sqrtf(tot), 1e-12f);
            signalCnt(&g_shot_done);
        } else if (task < T2E) {
            // ===== T2: MLP partials (wait mean) =====
            int s2 = task - T1E;
            int row = s2 / HCH, ch = s2 % HCH;
            float* SX = dyn; float* HP = dyn + CC; float* HID = dyn + CC + 8*HCW;
            const float *w1, *b1, *w2;
            waitCnt(&g_mean_done, T0N);
            if (row < BB) {
                w1 = w1t; b1 = b1t; w2 = w2t;
                float s = 0.0f;
#pragma unroll
                for (int n = 0; n < NN; n++)
#pragma unroll
                    for (int c2 = 0; c2 < MCH; c2++)
                        s += g_mean_part[((row * NN + n) * MCH + c2) * CC + tid];
                SX[tid] = s * (1.0f / (KT * NN));
            } else {
                int r = row - BB;
                w1 = w1c; b1 = b1c; w2 = w2c;
                float s = 0.0f;
#pragma unroll
                for (int c2 = 0; c2 < MCH; c2++)
                    s += g_mean_part[(r * MCH + c2) * CC + tid];
                SX[tid] = s * (1.0f / KT);
            }
            __syncthreads();

            int ce = tid / 48, jp = tid % 48, j0 = ch * HCW;
            u64 hp2 = 0ull;
            const float* w1b = w1 + j0 + jp * 2;
#pragma unroll 8
            for (int c = 0; c < 48; c++) {
                float x = SX[ce * 48 + c];
                u64 wv = *(const u64*)(w1b + (size_t)(ce * 48 + c) * HH);
                ffma2(hp2, pk2(x, x), wv);
            }
            {
                float h0, h1;
                unpk2(hp2, h0, h1);
                HP[ce * HCW + jp * 2]     = h0;
                HP[ce * HCW + jp * 2 + 1] = h1;
            }
            __syncthreads();
            if (tid < HCW) {
                float s = b1[j0 + tid];
#pragma unroll
                for (int e = 0; e < 8; e++) s += HP[e * HCW + tid];
                HID[tid] = fmaxf(s, 0.0f);
            }
            __syncthreads();

            float o = 0.0f;
            const float* w2p = w2 + (size_t)j0 * CC + tid;
#pragma unroll 8
            for (int j = 0; j < HCW; j++) o += HID[j] * w2p[(size_t)j * CC];
            g_mlp_part[(size_t)s2 * CC + tid] = o;
            signalCnt(&g_mlp_done);
        } else if (task < T3E) {
            // ===== T3: MLP finish (wait all mlp partials) =====
            int row = task - T2E;
            waitCnt(&g_mlp_done, T2N);
            float o = (row < BB) ? b2t[tid] : b2c[tid];
#pragma unroll
            for (int c2 = 0; c2 < HCH; c2++)
                o += g_mlp_part[(size_t)(row * HCH + c2) * CC + tid];
            if (row < BB) g_wt[row * CC + tid] = o;
            else          g_wc[(row - BB) * CC + tid] = sigm(o);
            signalCnt(&g_wcwt_done);
        } else if (task < T4E) {
            // ===== T4: shot map_s partials (wait wc/wt) =====
            int s2 = task - T3E;
            int bn = s2 / SCH, ch = s2 % SCH;
            int b = bn / NN;
            int t0 = ch * 40, t1 = min(KT, t0 + 40);
            float* SVV = dyn; float* PW = dyn + CC;
            waitCnt(&g_wcwt_done, NFIN);
            SVV[tid] = g_wc[bn * CC + tid] * g_wt[b * CC + tid];
            __syncthreads();

            float acc[12];
#pragma unroll
            for (int e = 0; e < 12; e++) acc[e] = 0.0f;
            for (int t = t0 + w; t < t1; t += NW) {
                const float* fp = fshot + ((size_t)bn * KT + t) * CC + 4 * lane;
                float fv[12];
#pragma unroll
                for (int j = 0; j < 3; j++) {
                    float4 u = *(const float4*)(fp + 128 * j);
                    fv[4*j] = u.x; fv[4*j+1] = u.y; fv[4*j+2] = u.z; fv[4*j+3] = u.w;
                }
                float r[1] = {0.0f};
#pragma unroll
                for (int j = 0; j < 3; j++) {
                    float4 u = *(const float4*)(&SVV[128 * j + 4 * lane]);
                    r[0] += fv[4*j]*u.x + fv[4*j+1]*u.y + fv[4*j+2]*u.z + fv[4*j+3]*u.w;
                }
                warpRed<1>(r);
                float ms = sigm(r[0]);
#pragma unroll
                for (int e = 0; e < 12; e++) acc[e] += fv[e] * ms;
            }
#pragma unroll
            for (int e = 0; e < 12; e++) {
                int c = 128 * (e >> 2) + (lane << 2) + (e & 3);
                PW[w * CC + c] = acc[e];
            }
            __syncthreads();
            float s = 0.0f;
#pragma unroll
            for (int ww = 0; ww < NW; ww++) s += PW[ww * CC + tid];
            g_shot_part[(size_t)s2 * CC + tid] = s;
            signalCnt(&g_shot_done);
        } else if (task < T5E) {
            // ===== T5: main fused pass (wait wc/wt; ns implied) =====
            int m = task - T4E;
            int b = m / (NCHK * NQG);
            int rem = m % (NCHK * NQG);
            int chunk = rem / NQG, qg = rem % NQG;
            int t0 = chunk * TQ;
            int q0 = b * QQ + qg * QG;
            float* SF  = dyn + OFF_SF;
            float* VV  = dyn + OFF_VV;
            float* NSS = dyn + OFF_NSS;
            float* SIM = dyn + OFF_SIM;
            // stage fshot chunk first (independent of wc/wt/ns)
            for (int i = tid; i < NN * TQ * (CC/4); i += 384) {
                int c4 = i % (CC/4), row = i / (CC/4);
                int n = row / TQ, t = row % TQ;
                float4 u = *(const float4*)(fshot + (((size_t)(b*NN+n))*KT + t0 + t)*CC + c4*4);
                *(float4*)(SF + row*RSTR + c4*4) = u;
            }
            waitCnt(&g_wcwt_done, NFIN);
            if (tid < NN * TQ) {
                int n = tid / TQ, t = tid % TQ;
                NSS[tid] = g_ns[(b * NN + n) * KT + t0 + t];
            }
            {
                float wtb = g_wt[b * CC + tid];
#pragma unroll
                for (int n = 0; n < NN; n++)
                    VV[n * RSTR + tid] = g_wc[(b * NN + n) * CC + tid] * wtb;
            }
            __syncthreads();

            const int g8 = lane >> 3, l8 = lane & 7;
            for (int base = w * 4; base < QG * TQ; base += NW * 4) {
                int item = base + g8;
                bool valid = item < QG * TQ;
                int it = valid ? item : QG * TQ - 1;
                int trel = it / QG, qi = it % QG;
                const float* fp = fq + ((size_t)(q0 + qi) * TT + t0 + trel) * CC + l8 * 4;
                u64 rp[11];
#pragma unroll
                for (int k = 0; k < 11; k++) rp[k] = 0ull;
#pragma unroll 4
                for (int i = 0; i < 12; i++) {
                    ulonglong2 a = *(const ulonglong2*)(fp + i * 32);
                    ffma2(rp[0], a.x, a.x);
                    ffma2(rp[0], a.y, a.y);
#pragma unroll
                    for (int n = 0; n < NN; n++) {
                        ulonglong2 u = *(const ulonglong2*)(SF + (n * TQ + trel) * RSTR + i * 32 + l8 * 4);
                        ffma2(rp[1 + n], a.x, u.x);
                        ffma2(rp[1 + n], a.y, u.y);
                        ulonglong2 v = *(const ulonglong2*)(VV + n * RSTR + i * 32 + l8 * 4);
                        ffma2(rp[6 + n], a.x, v.x);
                        ffma2(rp[6 + n], a.y, v.y);
                    }
                }
                float r[11];
#pragma unroll
                for (int k = 0; k < 11; k++) r[k] = upsum(rp[k]);
                segRed8<11>(r);
                if (l8 == 0 && valid) {
                    float nq = sqrtf(r[0]);
#pragma unroll
                    for (int n = 0; n < NN; n++) {
                        float den = fmaxf(nq * NSS[n * TQ + trel], 1e-8f);
                        SIM[(qi * NN + n) * TQ + trel] = r[1 + n] / den;
                        g_smq[((size_t)(q0 + qi) * NN + n) * TT + t0 + trel] = sigm(r[6 + n]);
                    }
                }
            }
            __syncthreads();

            if (tid < QG * NN) {
                int qi = tid / NN, n = tid % NN;
                float mm = -3.4e38f;
#pragma unroll
                for (int t = 0; t < TQ; t++)
                    mm = fmaxf(mm, SIM[(qi * NN + n) * TQ + t]);
                g_mx_part[((size_t)chunk * BQ + q0 + qi) * NN + n] = mm;
            }
            __threadfence();
            __syncthreads();
            if (tid < QG) atomicAdd(&g_bq_done[q0 + tid], 1u);
        } else {
            // ===== T6: finals (wait shot_done==60 and this bq's 28 chunks) =====
            int bq = task - T5E;
            int b = bq / QQ;
            float* SMQ5 = dyn;                      // NN*TT = 980
            float* PW4  = dyn + NN*TT;              // 4*NN*CC = 7680
            float* CW   = PW4 + 4*NN*CC;            // NW*21
            float* TOT  = CW + NW*21;
            if (tid == 0) {
                while (*(volatile unsigned*)&g_shot_done < (unsigned)SHOT_TGT) __nanosleep(32);
                while (*(volatile unsigned*)&g_bq_done[bq] < (unsigned)NCHK) __nanosleep(32);
            }
            __syncthreads();
            for (int i = tid; i < NN * TT; i += 384)
                SMQ5[i] = g_smq[(size_t)bq * NN * TT + i];
            __syncthreads();

            if (tid == 0) {
                float s = 0.0f;
#pragma unroll
                for (int n = 0; n < NN; n++) {
                    float mm = -3.4e38f;
                    for (int ch = 0; ch < NCHK; ch++)
                        mm = fmaxf(mm, g_mx_part[((size_t)ch * BQ + bq) * NN + n]);
                    s += mm;
                }
                s *= (1.0f / NN);
                out[bq] = s;
                out[BQ + bq] = s;
            }

            {
                int tq = tid / 96, c4 = tid % 96;
                u64 accp[NN][2];
#pragma unroll
                for (int n = 0; n < NN; n++) { accp[n][0] = 0ull; accp[n][1] = 0ull; }
                const float* fp4 = fq + ((size_t)bq * TT + tq * 49) * CC + c4 * 4;
#pragma unroll 7
                for (int t = 0; t < 49; t++) {
                    ulonglong2 a = *(const ulonglong2*)(fp4 + (size_t)t * CC);
#pragma unroll
                    for (int n = 0; n < NN; n++) {
                        float s = SMQ5[n * TT + tq * 49 + t];
                        u64 ss = pk2(s, s);
                        ffma2(accp[n][0], a.x, ss);
                        ffma2(accp[n][1], a.y, ss);
                    }
                }
#pragma unroll
                for (int n = 0; n < NN; n++) {
                    float l0, h0, l1, h1;
                    unpk2(accp[n][0], l0, h0);
                    unpk2(accp[n][1], l1, h1);
                    float* p = PW4 + (tq * NN + n) * CC + c4 * 4;
                    p[0] = l0; p[1] = h0; p[2] = l1; p[3] = h1;
                }
            }
            __syncthreads();

            float acc[NN];
#pragma unroll
            for (int n = 0; n < NN; n++) {
                float s = 0.0f;
#pragma unroll
                for (int q2 = 0; q2 < 4; q2++) s += PW4[(q2 * NN + n) * CC + tid];
                acc[n] = s;
            }

            float xqv = xq_in[(size_t)bq * CC + tid];
            float pv[21];
            pv[0] = xqv * xqv;
#pragma unroll
            for (int n = 0; n < NN; n++) {
                float wcv = g_wc[(b * NN + n) * CC + tid];
                float sp = 0.0f;
#pragma unroll
                for (int ch = 0; ch < SCH; ch++)
                    sp += g_shot_part[(size_t)((b * NN + n) * SCH + ch) * CC + tid];
                float xsr = wcv * sp * (1.0f / KT);
                float xqr = wcv * acc[n] * (1.0f / TT);
                pv[1 + n]  = xqv * g_xs2_hat[(b * NN + n) * CC + tid];
                pv[6 + n]  = xqr * xqr;
                pv[11 + n] = xqr * xsr;
                pv[16 + n] = xsr * xsr;
            }
            warpRed<21>(pv);
            if (lane == 0) {
#pragma unroll
                for (int k = 0; k < 21; k++) CW[w * 21 + k] = pv[k];
            }
            __syncthreads();
            if (tid < 21) {
                float s = 0.0f;
#pragma unroll
                for (int ww = 0; ww < NW; ww++) s += CW[ww * 21 + tid];
                TOT[tid] = s;
            }
            __syncthreads();
            if (tid < NN) {
                float nq2 = fmaxf(sqrtf(TOT[0]), 1e-12f);
                out[2 * BQ + bq * NN + tid] = TEMPF * TOT[1 + tid] / nq2;
                out[2 * BQ + BQ * NN + bq * NN + tid] =
                    TOT[11 + tid] / ((1e-16f + sqrtf(TOT[6 + tid])) * (1e-16f + sqrtf(TOT[16 + tid])));
            }
        }
    }

    // all work done: reset counters for next graph replay (after full drain)
    gridBar();
    if (blockIdx.x == 0) {
        if (tid < BQ) g_bq_done[tid] = 0u;
        if (tid == 0) {
            g_mean_done = 0u; g_mlp_done = 0u;
            g_wcwt_done = 0u; g_shot_done = 0u;
        }
    }
}

extern "C" void kernel_launch(void* const* d_in, const int* in_sizes, int n_in,
                              void* d_out, int out_size) {
    const float* feat_shot  = (const float*)d_in[0];
    const float* feat_query = (const float*)d_in[1];
    const float* x_shot     = (const float*)d_in[2];
    const float* x_query    = (const float*)d_in[3];
    const float* w1_task    = (const float*)d_in[4];
    const float* b1_task    = (const float*)d_in[5];
    const float* w2_task    = (const float*)d_in[6];
    const float* b2_task    = (const float*)d_in[7];
    const float* w1_cls     = (const float*)d_in[8];
    const float* b1_cls     = (const float*)d_in[9];
    const float* w2_cls     = (const float*)d_in[10];
    const float* b2_cls     = (const float*)d_in[11];
    float* out = (float*)d_out;

    cudaFuncSetAttribute(kFused, cudaFuncAttributeMaxDynamicSharedMemorySize, DYN_BYTES);

    int dev = 0;
    cudaGetDevice(&dev);
    int sms = 0;
    cudaDeviceGetAttribute(&sms, cudaDevAttrMultiProcessorCount, dev);
    int maxBlk = 1;
    cudaOccupancyMaxActiveBlocksPerMultiprocessor(&maxBlk, kFused, 384, DYN_BYTES);
    if (maxBlk < 1) maxBlk = 1;
    int grid = sms * maxBlk;

    kFused<<<grid, 384, DYN_BYTES>>>(feat_shot, feat_query, x_shot, x_query,
                                     w1_task, b1_task, w2_task, b2_task,
                                     w1_cls, b1_cls, w2_cls, b2_cls, out);
}

// round 14
// speedup vs baseline: 2.0331x; 1.0005x over previous
#include <cuda_runtime.h>
#include <math.h>

#define BB 2
#define QQ 75
#define NN 5
#define KK 1
#define TT 196
#define CC 384
#define HH 1536
#define KT 196
#define BQ 150
#define TEMPF 10.0f

#define MCH 7          // t-chunks for fused mean+ns pass (28 rows)
#define SCH 5          // t-chunks for shot map_s pass (40/36 rows)
#define HCH 16         // hidden chunks for MLP (96 units)
#define HCW 96
#define TQ 7           // t-chunk for main pass
#define NCHK 28        // TT / TQ
#define QG 25          // queries per group
#define NQG 3          // QQ / QG
#define NW 12          // warps per block (384 threads)
#define RSTR 392       // padded row stride (floats) for SF/VV
#define NFIN (BB + BB*NN)   // 12 MLP-finish tasks

// ---- task stream layout (main BEFORE shot) ----
#define T0N (BB*NN*MCH)            // 70  mean+ns
#define T1N (BB*NN)                // 10  xs2_hat
#define T2N ((BB + BB*NN)*HCH)     // 192 MLP partials
#define T3N NFIN                   // 12  MLP finish
#define T5N (BB*NCHK*NQG)          // 168 main pass
#define T4N (BB*NN*SCH)            // 50  shot map_s
#define T6N BQ                     // 150 finals
#define T0E T0N
#define T1E (T0E + T1N)
#define T2E (T1E + T2N)
#define T3E (T2E + T3N)            // 284
#define T5E (T3E + T5N)            // 452 (main)
#define T4E (T5E + T4N)            // 502 (shot)
#define T6E (T4E + T6N)            // 652
#define SHOT_TGT (T4N + T1N)       // 60 (xs2 folded in)

// ---- dynamic smem layout (floats) ----
#define OFF_SF   0                         // NN*TQ*RSTR = 13720
#define OFF_VV   (OFF_SF + NN*TQ*RSTR)     // NN*RSTR = 1960
#define OFF_NSS  (OFF_VV + NN*RSTR)        // NN*TQ = 35
#define OFF_SIM  (OFF_NSS + NN*TQ)         // QG*NN*TQ = 875
#define DYN_FLOATS (OFF_SIM + QG*NN*TQ)    // 16590
#define DYN_BYTES  (DYN_FLOATS * 4)

typedef unsigned long long u64;

// ---------------- persistent scratch ----------------
__device__ float g_mean_part[BB*NN*MCH*CC];
__device__ float g_mlp_part[(BB + BB*NN)*HCH*CC];
__device__ float g_wt[BB*CC];
__device__ float g_wc[BB*NN*CC];
__device__ float g_ns[BB*NN*KT];
__device__ float g_shot_part[BB*NN*SCH*CC];
__device__ float g_xs2_hat[BB*NN*CC];
__device__ float g_smq[BQ*NN*TT];
__device__ float g_mx_part[NCHK*BQ*NN];
__device__ unsigned g_bar_cnt;
__device__ unsigned g_bar_gen;
__device__ unsigned g_meanbn_done[BB*NN];   // -> 7 each
__device__ unsigned g_mlprow_done[NFIN];    // -> 16 each
__device__ unsigned g_wcwt_done;            // -> 12
__device__ unsigned g_shot_done;            // -> 60
__device__ unsigned g_bq_done[BQ];          // -> 28 each

template<int NV>
__device__ __forceinline__ void warpRed(float* v) {
#pragma unroll
    for (int off = 16; off; off >>= 1) {
#pragma unroll
        for (int k = 0; k < NV; k++)
            v[k] += __shfl_xor_sync(0xffffffffu, v[k], off);
    }
}

template<int NV>
__device__ __forceinline__ void segRed8(float* v) {
#pragma unroll
    for (int off = 4; off; off >>= 1) {
#pragma unroll
        for (int k = 0; k < NV; k++)
            v[k] += __shfl_xor_sync(0xffffffffu, v[k], off);
    }
}

__device__ __forceinline__ void ffma2(u64& d, u64 a, u64 b) {
    asm("fma.rn.f32x2 %0, %1, %2, %0;" : "+l"(d) : "l"(a), "l"(b));
}
__device__ __forceinline__ float upsum(u64 v) {
    float lo, hi;
    asm("mov.b64 {%0, %1}, %2;" : "=f"(lo), "=f"(hi) : "l"(v));
    return lo + hi;
}
__device__ __forceinline__ void unpk2(u64 v, float& lo, float& hi) {
    asm("mov.b64 {%0, %1}, %2;" : "=f"(lo), "=f"(hi) : "l"(v));
}
__device__ __forceinline__ u64 pk2(float a, float b) {
    u64 r;
    asm("mov.b64 %0, {%1, %2};" : "=l"(r) : "f"(a), "f"(b));
    return r;
}
__device__ __forceinline__ void pfL2(const void* p) {
    asm volatile("prefetch.global.L2 [%0];" :: "l"(p));
}

__device__ __forceinline__ float sigm(float x) {
    return 1.0f / (1.0f + __expf(-x));
}

__device__ __forceinline__ void gridBar() {
    __syncthreads();
    if (threadIdx.x == 0) {
        __threadfence();
        unsigned gen = *(volatile unsigned*)&g_bar_gen;
        if (atomicAdd(&g_bar_cnt, 1u) == gridDim.x - 1u) {
            g_bar_cnt = 0u;
            __threadfence();
            atomicAdd(&g_bar_gen, 1u);
        } else {
            while (*(volatile unsigned*)&g_bar_gen == gen) __nanosleep(64);
        }
        __threadfence();
    }
    __syncthreads();
}

__device__ __forceinline__ void waitCnt(unsigned* c, unsigned target) {
    if (threadIdx.x == 0) {
        while (*(volatile unsigned*)c < target) __nanosleep(32);
    }
    __syncthreads();
}

__device__ __forceinline__ void signalCnt(unsigned* c) {
    __threadfence();
    __syncthreads();
    if (threadIdx.x == 0) atomicAdd(c, 1u);
}

__global__ __launch_bounds__(384, 2) void kFused(
    const float* __restrict__ fshot, const float* __restrict__ fq,
    const float* __restrict__ x_shot, const float* __restrict__ xq_in,
    const float* __restrict__ w1t, const float* __restrict__ b1t,
    const float* __restrict__ w2t, const float* __restrict__ b2t,
    const float* __restrict__ w1c, const float* __restrict__ b1c,
    const float* __restrict__ w2c, const float* __restrict__ b2c,
    float* __restrict__ out) {
    extern __shared__ float dyn[];
    const int tid = threadIdx.x;
    const int w = tid >> 5, lane = tid & 31;

    for (int task = blockIdx.x; task < T6E; task += gridDim.x) {
        __syncthreads();   // protect dyn reuse between tasks
        if (task < T0E) {
            // ===== T0: fused mean + ns partials =====
            int bn = task / MCH, ch = task % MCH;
            int t0 = ch * 28;
            float* PW = dyn;
            float acc[12];
#pragma unroll
            for (int e = 0; e < 12; e++) acc[e] = 0.0f;
            for (int t = t0 + w; t < t0 + 28; t += NW) {
                const float* fp = fshot + ((size_t)bn * KT + t) * CC + 4 * lane;
                float fv[12];
#pragma unroll
                for (int j = 0; j < 3; j++) {
                    float4 u = *(const float4*)(fp + 128 * j);
                    fv[4*j] = u.x; fv[4*j+1] = u.y; fv[4*j+2] = u.z; fv[4*j+3] = u.w;
                }
                float r[1] = {0.0f};
#pragma unroll
                for (int e = 0; e < 12; e++) r[0] += fv[e] * fv[e];
                warpRed<1>(r);
                if (lane == 0) g_ns[bn * KT + t] = sqrtf(r[0]);
#pragma unroll
                for (int e = 0; e < 12; e++) acc[e] += fv[e];
            }
#pragma unroll
            for (int e = 0; e < 12; e++) {
                int c = 128 * (e >> 2) + (lane << 2) + (e & 3);
                PW[w * CC + c] = acc[e];
            }
            __syncthreads();
            float s = 0.0f;
#pragma unroll
            for (int ww = 0; ww < NW; ww++) s += PW[ww * CC + tid];
            g_mean_part[(bn * MCH + ch) * CC + tid] = s;
            signalCnt(&g_meanbn_done[bn]);
        } else if (task < T1E) {
            // ===== T1: plain prototype (counts toward shot_done) =====
            int bn = task - T0E;
            float xm = x_shot[(size_t)bn * CC + tid];  // KK=1
            float r[1] = {xm * xm};
            warpRed<1>(r);
            if (lane == 0) dyn[w] = r[0];
            __syncthreads();
            float tot = 0.0f;
#pragma unroll
            for (int ww = 0; ww < NW; ww++) tot += dyn[ww];
            g_xs2_hat[bn * CC + tid] = xm / fmaxf(sqrtf(tot), 1e-12f);
            signalCnt(&g_shot_done);
        } else if (task < T2E) {
            // ===== T2: MLP partials (prefetch weights, wait only own bn(s)) =====
            int s2 = task - T1E;
            int row = s2 / HCH, ch = s2 % HCH;
            float* SX = dyn; float* HP = dyn + CC; float* HID = dyn + CC + 8*HCW;
            const float *w1, *b1, *w2;
            if (row < BB) { w1 = w1t; b1 = b1t; w2 = w2t; }
            else          { w1 = w1c; b1 = b1c; w2 = w2c; }

            int ce = tid / 48, jp = tid % 48, j0 = ch * HCW;
            const float* w1b = w1 + j0 + jp * 2;
            const float* w2p = w2 + (size_t)j0 * CC + tid;
            // L2 prefetch of this task's weight chunk BEFORE the dependency wait
#pragma unroll 8
            for (int c = 0; c < 48; c++) pfL2(w1b + (size_t)(ce * 48 + c) * HH);
#pragma unroll 8
            for (int j = ce; j < HCW; j += 8) pfL2(w2p + (size_t)j * CC);

            if (tid == 0) {
                if (row < BB) {
#pragma unroll
                    for (int n = 0; n < NN; n++)
                        while (*(volatile unsigned*)&g_meanbn_done[row * NN + n] < (unsigned)MCH) __nanosleep(32);
                } else {
                    while (*(volatile unsigned*)&g_meanbn_done[row - BB] < (unsigned)MCH) __nanosleep(32);
                }
            }
            __syncthreads();

            if (row < BB) {
                float s = 0.0f;
#pragma unroll
                for (int n = 0; n < NN; n++)
#pragma unroll
                    for (int c2 = 0; c2 < MCH; c2++)
                        s += g_mean_part[((row * NN + n) * MCH + c2) * CC + tid];
                SX[tid] = s * (1.0f / (KT * NN));
            } else {
                int r = row - BB;
                float s = 0.0f;
#pragma unroll
                for (int c2 = 0; c2 < MCH; c2++)
                    s += g_mean_part[(r * MCH + c2) * CC + tid];
                SX[tid] = s * (1.0f / KT);
            }
            __syncthreads();

            u64 hp2 = 0ull;
#pragma unroll 8
            for (int c = 0; c < 48; c++) {
                float x = SX[ce * 48 + c];
                u64 wv = *(const u64*)(w1b + (size_t)(ce * 48 + c) * HH);
                ffma2(hp2, pk2(x, x), wv);
            }
            {
                float h0, h1;
                unpk2(hp2, h0, h1);
                HP[ce * HCW + jp * 2]     = h0;
                HP[ce * HCW + jp * 2 + 1] = h1;
            }
            __syncthreads();
            if (tid < HCW) {
                float s = b1[j0 + tid];
#pragma unroll
                for (int e = 0; e < 8; e++) s += HP[e * HCW + tid];
                HID[tid] = fmaxf(s, 0.0f);
            }
            __syncthreads();

            float o = 0.0f;
#pragma unroll 8
            for (int j = 0; j < HCW; j++) o += HID[j] * w2p[(size_t)j * CC];
            g_mlp_part[(size_t)s2 * CC + tid] = o;
            signalCnt(&g_mlprow_done[row]);
        } else if (task < T3E) {
            // ===== T3: MLP finish (wait only own row's partials) =====
            int row = task - T2E;
            waitCnt(&g_mlprow_done[row], HCH);
            float o = (row < BB) ? b2t[tid] : b2c[tid];
#pragma unroll
            for (int c2 = 0; c2 < HCH; c2++)
                o += g_mlp_part[(size_t)(row * HCH + c2) * CC + tid];
            if (row < BB) g_wt[row * CC + tid] = o;
            else          g_wc[(row - BB) * CC + tid] = sigm(o);
            signalCnt(&g_wcwt_done);
        } else if (task < T5E) {
            // ===== T5: main fused pass (wait wc/wt; ns implied) =====
            int m = task - T3E;
            int b = m / (NCHK * NQG);
            int rem = m % (NCHK * NQG);
            int chunk = rem / NQG, qg = rem % NQG;
            int t0 = chunk * TQ;
            int q0 = b * QQ + qg * QG;
            float* SF  = dyn + OFF_SF;
            float* VV  = dyn + OFF_VV;
            float* NSS = dyn + OFF_NSS;
            float* SIM = dyn + OFF_SIM;
            // stage fshot chunk first (independent of wc/wt/ns)
            for (int i = tid; i < NN * TQ * (CC/4); i += 384) {
                int c4 = i % (CC/4), row = i / (CC/4);
                int n = row / TQ, t = row % TQ;
                float4 u = *(const float4*)(fshot + (((size_t)(b*NN+n))*KT + t0 + t)*CC + c4*4);
                *(float4*)(SF + row*RSTR + c4*4) = u;
            }
            waitCnt(&g_wcwt_done, NFIN);
            if (tid < NN * TQ) {
                int n = tid / TQ, t = tid % TQ;
                NSS[tid] = g_ns[(b * NN + n) * KT + t0 + t];
            }
            {
                float wtb = g_wt[b * CC + tid];
#pragma unroll
                for (int n = 0; n < NN; n++)
                    VV[n * RSTR + tid] = g_wc[(b * NN + n) * CC + tid] * wtb;
            }
            __syncthreads();

            const int g8 = lane >> 3, l8 = lane & 7;
            for (int base = w * 4; base < QG * TQ; base += NW * 4) {
                int item = base + g8;
                bool valid = item < QG * TQ;
                int it = valid ? item : QG * TQ - 1;
                int trel = it / QG, qi = it % QG;
                const float* fp = fq + ((size_t)(q0 + qi) * TT + t0 + trel) * CC + l8 * 4;
                u64 rp[11];
#pragma unroll
                for (int k = 0; k < 11; k++) rp[k] = 0ull;
#pragma unroll 4
                for (int i = 0; i < 12; i++) {
                    ulonglong2 a = *(const ulonglong2*)(fp + i * 32);
                    ffma2(rp[0], a.x, a.x);
                    ffma2(rp[0], a.y, a.y);
#pragma unroll
                    for (int n = 0; n < NN; n++) {
                        ulonglong2 u = *(const ulonglong2*)(SF + (n * TQ + trel) * RSTR + i * 32 + l8 * 4);
                        ffma2(rp[1 + n], a.x, u.x);
                        ffma2(rp[1 + n], a.y, u.y);
                        ulonglong2 v = *(const ulonglong2*)(VV + n * RSTR + i * 32 + l8 * 4);
                        ffma2(rp[6 + n], a.x, v.x);
                        ffma2(rp[6 + n], a.y, v.y);
                    }
                }
                float r[11];
#pragma unroll
                for (int k = 0; k < 11; k++) r[k] = upsum(rp[k]);
                segRed8<11>(r);
                if (l8 == 0 && valid) {
                    float nq = sqrtf(r[0]);
#pragma unroll
                    for (int n = 0; n < NN; n++) {
                        float den = fmaxf(nq * NSS[n * TQ + trel], 1e-8f);
                        SIM[(qi * NN + n) * TQ + trel] = r[1 + n] / den;
                        g_smq[((size_t)(q0 + qi) * NN + n) * TT + t0 + trel] = sigm(r[6 + n]);
                    }
                }
            }
            __syncthreads();

            if (tid < QG * NN) {
                int qi = tid / NN, n = tid % NN;
                float mm = -3.4e38f;
#pragma unroll
                for (int t = 0; t < TQ; t++)
                    mm = fmaxf(mm, SIM[(qi * NN + n) * TQ + t]);
                g_mx_part[((size_t)chunk * BQ + q0 + qi) * NN + n] = mm;
            }
            __threadfence();
            __syncthreads();
            if (tid < QG) atomicAdd(&g_bq_done[q0 + tid], 1u);
        } else if (task < T4E) {
            // ===== T4: shot map_s partials (wait wc/wt) =====
            int s2 = task - T5E;
            int bn = s2 / SCH, ch = s2 % SCH;
            int b = bn / NN;
            int t0 = ch * 40, t1 = min(KT, t0 + 40);
            float* SVV = dyn; float* PW = dyn + CC;
            waitCnt(&g_wcwt_done, NFIN);
            SVV[tid] = g_wc[bn * CC + tid] * g_wt[b * CC + tid];
            __syncthreads();

            float acc[12];
#pragma unroll
            for (int e = 0; e < 12; e++) acc[e] = 0.0f;
            for (int t = t0 + w; t < t1; t += NW) {
                const float* fp = fshot + ((size_t)bn * KT + t) * CC + 4 * lane;
                float fv[12];
#pragma unroll
                for (int j = 0; j < 3; j++) {
                    float4 u = *(const float4*)(fp + 128 * j);
                    fv[4*j] = u.x; fv[4*j+1] = u.y; fv[4*j+2] = u.z; fv[4*j+3] = u.w;
                }
                float r[1] = {0.0f};
#pragma unroll
                for (int j = 0; j < 3; j++) {
                    float4 u = *(const float4*)(&SVV[128 * j + 4 * lane]);
                    r[0] += fv[4*j]*u.x + fv[4*j+1]*u.y + fv[4*j+2]*u.z + fv[4*j+3]*u.w;
                }
                warpRed<1>(r);
                float ms = sigm(r[0]);
#pragma unroll
                for (int e = 0; e < 12; e++) acc[e] += fv[e] * ms;
            }
#pragma unroll
            for (int e = 0; e < 12; e++) {
                int c = 128 * (e >> 2) + (lane << 2) + (e & 3);
                PW[w * CC + c] = acc[e];
            }
            __syncthreads();
            float s = 0.0f;
#pragma unroll
            for (int ww = 0; ww < NW; ww++) s += PW[ww * CC + tid];
            g_shot_part[(size_t)s2 * CC + tid] = s;
            signalCnt(&g_shot_done);
        } else {
            // ===== T6: finals (wait shot_done==60 and this bq's 28 chunks) =====
            int bq = task - T4E;
            int b = bq / QQ;
            float* SMQ5 = dyn;                      // NN*TT = 980
            float* PW4  = dyn + NN*TT;              // 4*NN*CC = 7680
            float* CW   = PW4 + 4*NN*CC;            // NW*21
            float* TOT  = CW + NW*21;
            if (tid == 0) {
                while (*(volatile unsigned*)&g_shot_done < (unsigned)SHOT_TGT) __nanosleep(32);
                while (*(volatile unsigned*)&g_bq_done[bq] < (unsigned)NCHK) __nanosleep(32);
            }
            __syncthreads();
            for (int i = tid; i < NN * TT; i += 384)
                SMQ5[i] = g_smq[(size_t)bq * NN * TT + i];
            __syncthreads();

            if (tid == 0) {
                float s = 0.0f;
#pragma unroll
                for (int n = 0; n < NN; n++) {
                    float mm = -3.4e38f;
                    for (int ch = 0; ch < NCHK; ch++)
                        mm = fmaxf(mm, g_mx_part[((size_t)ch * BQ + bq) * NN + n]);
                    s += mm;
                }
                s *= (1.0f / NN);
                out[bq] = s;
                out[BQ + bq] = s;
            }

            {
                int tq = tid / 96, c4 = tid % 96;
                u64 accp[NN][2];
#pragma unroll
                for (int n = 0; n < NN; n++) { accp[n][0] = 0ull; accp[n][1] = 0ull; }
                const float* fp4 = fq + ((size_t)bq * TT + tq * 49) * CC + c4 * 4;
#pragma unroll 7
                for (int t = 0; t < 49; t++) {
                    ulonglong2 a = *(const ulonglong2*)(fp4 + (size_t)t * CC);
#pragma unroll
                    for (int n = 0; n < NN; n++) {
                        float s = SMQ5[n * TT + tq * 49 + t];
                        u64 ss = pk2(s, s);
                        ffma2(accp[n][0], a.x, ss);
                        ffma2(accp[n][1], a.y, ss);
                    }
                }
#pragma unroll
                for (int n = 0; n < NN; n++) {
                    float l0, h0, l1, h1;
                    unpk2(accp[n][0], l0, h0);
                    unpk2(accp[n][1], l1, h1);
                    float* p = PW4 + (tq * NN + n) * CC + c4 * 4;
                    p[0] = l0; p[1] = h0; p[2] = l1; p[3] = h1;
                }
            }
            __syncthreads();

            float acc[NN];
#pragma unroll
            for (int n = 0; n < NN; n++) {
                float s = 0.0f;
#pragma unroll
                for (int q2 = 0; q2 < 4; q2++) s += PW4[(q2 * NN + n) * CC + tid];
                acc[n] = s;
            }

            float xqv = xq_in[(size_t)bq * CC + tid];
            float pv[21];
            pv[0] = xqv * xqv;
#pragma unroll
            for (int n = 0; n < NN; n++) {
                float wcv = g_wc[(b * NN + n) * CC + tid];
                float sp = 0.0f;
#pragma unroll
                for (int ch = 0; ch < SCH; ch++)
                    sp += g_shot_part[(size_t)((b * NN + n) * SCH + ch) * CC + tid];
                float xsr = wcv * sp * (1.0f / KT);
                float xqr = wcv * acc[n] * (1.0f / TT);
                pv[1 + n]  = xqv * g_xs2_hat[(b * NN + n) * CC + tid];
                pv[6 + n]  = xqr * xqr;
                pv[11 + n] = xqr * xsr;
                pv[16 + n] = xsr * xsr;
            }
            warpRed<21>(pv);
            if (lane == 0) {
#pragma unroll
                for (int k = 0; k < 21; k++) CW[w * 21 + k] = pv[k];
            }
            __syncthreads();
            if (tid < 21) {
                float s = 0.0f;
#pragma unroll
                for (int ww = 0; ww < NW; ww++) s += CW[ww * 21 + tid];
                TOT[tid] = s;
            }
            __syncthreads();
            if (tid < NN) {
                float nq2 = fmaxf(sqrtf(TOT[0]), 1e-12f);
                out[2 * BQ + bq * NN + tid] = TEMPF * TOT[1 + tid] / nq2;
                out[2 * BQ + BQ * NN + bq * NN + tid] =
                    TOT[11 + tid] / ((1e-16f + sqrtf(TOT[6 + tid])) * (1e-16f + sqrtf(TOT[16 + tid])));
            }
        }
    }

    // all work done: reset counters for next graph replay (after full drain)
    gridBar();
    if (blockIdx.x == 0) {
        if (tid < BQ) g_bq_done[tid] = 0u;
        if (tid < BB*NN) g_meanbn_done[tid] = 0u;
        if (tid < NFIN) g_mlprow_done[tid] = 0u;
        if (tid == 0) { g_wcwt_done = 0u; g_shot_done = 0u; }
    }
}

extern "C" void kernel_launch(void* const* d_in, const int* in_sizes, int n_in,
                              void* d_out, int out_size) {
    const float* feat_shot  = (const float*)d_in[0];
    const float* feat_query = (const float*)d_in[1];
    const float* x_shot     = (const float*)d_in[2];
    const float* x_query    = (const float*)d_in[3];
    const float* w1_task    = (const float*)d_in[4];
    const float* b1_task    = (const float*)d_in[5];
    const float* w2_task    = (const float*)d_in[6];
    const float* b2_task    = (const float*)d_in[7];
    const float* w1_cls     = (const float*)d_in[8];
    const float* b1_cls     = (const float*)d_in[9];
    const float* w2_cls     = (const float*)d_in[10];
    const float* b2_cls     = (const float*)d_in[11];
    float* out = (float*)d_out;

    cudaFuncSetAttribute(kFused, cudaFuncAttributeMaxDynamicSharedMemorySize, DYN_BYTES);

    int dev = 0;
    cudaGetDevice(&dev);
    int sms = 0;
    cudaDeviceGetAttribute(&sms, cudaDevAttrMultiProcessorCount, dev);
    int maxBlk = 1;
    cudaOccupancyMaxActiveBlocksPerMultiprocessor(&maxBlk, kFused, 384, DYN_BYTES);
    if (maxBlk < 1) maxBlk = 1;
    int grid = sms * maxBlk;

    kFused<<<grid, 384, DYN_BYTES>>>(feat_shot, feat_query, x_shot, x_query,
                                     w1_task, b1_task, w2_task, b2_task,
                                     w1_cls, b1_cls, w2_cls, b2_cls, out);
}

// round 15
// speedup vs baseline: 2.4370x; 1.1986x over previous
#include <cuda_runtime.h>
#include <math.h>

#define BB 2
#define QQ 75
#define NN 5
#define KK 1
#define TT 196
#define CC 384
#define HH 1536
#define KT 196
#define BQ 150
#define TEMPF 10.0f

#define MCH 7          // t-chunks for fused mean+ns pass (28 rows)
#define SCH 5          // t-chunks for shot map_s pass (40/36 rows)
#define HCH 16         // hidden chunks for MLP (96 units)
#define HCW 96
#define TQ 7           // t-chunk for main pass
#define NCHK 28        // TT / TQ
#define QG 25          // queries per group
#define NQG 3          // QQ / QG
#define NW 12          // warps per block (384 threads)
#define NFIN (BB + BB*NN)   // 12 MLP-finish tasks

// ---- task stream ids ----
#define T0N (BB*NN*MCH)            // 70  mean+ns
#define T1N (BB*NN)                // 10  xs2_hat
#define T2N ((BB + BB*NN)*HCH)     // 192 MLP partials
#define T3N NFIN                   // 12  MLP finish
#define TAN (BB*NCHK*NQG)          // 168 main num/SIM (T5a)
#define TBN (BB*NCHK*NQG)          // 168 main map_q (T5b)
#define T4N (BB*NN*SCH)            // 50  shot map_s
#define T6N BQ                     // 150 finals
#define T0E T0N                    // 70
#define T1E (T0E + T1N)            // 80
#define T2E (T1E + T2N)            // 272
#define T3E (T2E + T3N)            // 284
#define TAE (T3E + TAN)            // 452
#define TBE (TAE + TBN)            // 620
#define T4E (TBE + T4N)            // 670
#define T6E (T4E + T6N)            // 820
#define SHOT_TGT (T4N + T1N)       // 60
#define BQ_TGT (2*NCHK)            // 56 (28 from T5a + 28 from T5b)

// ---- dynamic smem (floats): max over task types ----
// T0: NW*CC=4608 | T2: 384+768+96 | T5a: 875+175+35=1085 | T5b: 1920
// T4: 384+4608=4992 | T6: 980+7680+252+21=8933
#define DYN_FLOATS 8960
#define DYN_BYTES  (DYN_FLOATS * 4)

typedef unsigned long long u64;

// ---------------- persistent scratch ----------------
__device__ float g_mean_part[BB*NN*MCH*CC];
__device__ float g_mlp_part[(BB + BB*NN)*HCH*CC];
__device__ float g_wt[BB*CC];
__device__ float g_wc[BB*NN*CC];
__device__ float g_ns[BB*NN*KT];
__device__ float g_shot_part[BB*NN*SCH*CC];
__device__ float g_xs2_hat[BB*NN*CC];
__device__ float g_smq[BQ*NN*TT];
__device__ float g_mx_part[NCHK*BQ*NN];
__device__ unsigned g_bar_cnt;
__device__ unsigned g_bar_gen;
__device__ unsigned g_task;                 // dynamic task counter
__device__ unsigned g_meanbn_done[BB*NN];   // -> 7 each
__device__ unsigned g_meanb_done[BB];       // -> 35 each
__device__ unsigned g_mlprow_done[NFIN];    // -> 16 each
__device__ unsigned g_wcwt_done;            // -> 12
__device__ unsigned g_shot_done;            // -> 60
__device__ unsigned g_bq_done[BQ];          // -> 56 each

template<int NV>
__device__ __forceinline__ void warpRed(float* v) {
#pragma unroll
    for (int off = 16; off; off >>= 1) {
#pragma unroll
        for (int k = 0; k < NV; k++)
            v[k] += __shfl_xor_sync(0xffffffffu, v[k], off);
    }
}

template<int NV>
__device__ __forceinline__ void segRed8(float* v) {
#pragma unroll
    for (int off = 4; off; off >>= 1) {
#pragma unroll
        for (int k = 0; k < NV; k++)
            v[k] += __shfl_xor_sync(0xffffffffu, v[k], off);
    }
}

__device__ __forceinline__ void ffma2(u64& d, u64 a, u64 b) {
    asm("fma.rn.f32x2 %0, %1, %2, %0;" : "+l"(d) : "l"(a), "l"(b));
}
__device__ __forceinline__ float upsum(u64 v) {
    float lo, hi;
    asm("mov.b64 {%0, %1}, %2;" : "=f"(lo), "=f"(hi) : "l"(v));
    return lo + hi;
}
__device__ __forceinline__ void unpk2(u64 v, float& lo, float& hi) {
    asm("mov.b64 {%0, %1}, %2;" : "=f"(lo), "=f"(hi) : "l"(v));
}
__device__ __forceinline__ u64 pk2(float a, float b) {
    u64 r;
    asm("mov.b64 %0, {%1, %2};" : "=l"(r) : "f"(a), "f"(b));
    return r;
}
__device__ __forceinline__ void pfL2(const void* p) {
    asm volatile("prefetch.global.L2 [%0];" :: "l"(p));
}

__device__ __forceinline__ float sigm(float x) {
    return 1.0f / (1.0f + __expf(-x));
}

__device__ __forceinline__ void gridBar() {
    __syncthreads();
    if (threadIdx.x == 0) {
        __threadfence();
        unsigned gen = *(volatile unsigned*)&g_bar_gen;
        if (atomicAdd(&g_bar_cnt, 1u) == gridDim.x - 1u) {
            g_bar_cnt = 0u;
            __threadfence();
            atomicAdd(&g_bar_gen, 1u);
        } else {
            while (*(volatile unsigned*)&g_bar_gen == gen) __nanosleep(64);
        }
        __threadfence();
    }
    __syncthreads();
}

__device__ __forceinline__ void waitCnt(unsigned* c, unsigned target) {
    if (threadIdx.x == 0) {
        while (*(volatile unsigned*)c < target) __nanosleep(32);
    }
    __syncthreads();
}

__device__ __forceinline__ void signal1(unsigned* c) {
    __threadfence();
    __syncthreads();
    if (threadIdx.x == 0) atomicAdd(c, 1u);
}

__global__ __launch_bounds__(384, 2) void kFused(
    const float* __restrict__ fshot, const float* __restrict__ fq,
    const float* __restrict__ x_shot, const float* __restrict__ xq_in,
    const float* __restrict__ w1t, const float* __restrict__ b1t,
    const float* __restrict__ w2t, const float* __restrict__ b2t,
    const float* __restrict__ w1c, const float* __restrict__ b1c,
    const float* __restrict__ w2c, const float* __restrict__ b2c,
    float* __restrict__ out) {
    extern __shared__ float dyn[];
    __shared__ int s_task;
    const int tid = threadIdx.x;
    const int w = tid >> 5, lane = tid & 31;
    const size_t NSTRIDE = (size_t)KT * CC;   // fshot n-stride

    while (1) {
        __syncthreads();
        if (tid == 0) s_task = (int)atomicAdd(&g_task, 1u);
        __syncthreads();
        int task = s_task;
        if (task >= T6E) break;

        if (task < T0E) {
            // ===== T0: fused mean + ns partials =====
            int bn = task / MCH, ch = task % MCH;
            int t0 = ch * 28;
            float* PW = dyn;
            float acc[12];
#pragma unroll
            for (int e = 0; e < 12; e++) acc[e] = 0.0f;
            for (int t = t0 + w; t < t0 + 28; t += NW) {
                const float* fp = fshot + ((size_t)bn * KT + t) * CC + 4 * lane;
                float fv[12];
#pragma unroll
                for (int j = 0; j < 3; j++) {
                    float4 u = *(const float4*)(fp + 128 * j);
                    fv[4*j] = u.x; fv[4*j+1] = u.y; fv[4*j+2] = u.z; fv[4*j+3] = u.w;
                }
                float r[1] = {0.0f};
#pragma unroll
                for (int e = 0; e < 12; e++) r[0] += fv[e] * fv[e];
                warpRed<1>(r);
                if (lane == 0) g_ns[bn * KT + t] = sqrtf(r[0]);
#pragma unroll
                for (int e = 0; e < 12; e++) acc[e] += fv[e];
            }
#pragma unroll
            for (int e = 0; e < 12; e++) {
                int c = 128 * (e >> 2) + (lane << 2) + (e & 3);
                PW[w * CC + c] = acc[e];
            }
            __syncthreads();
            float s = 0.0f;
#pragma unroll
            for (int ww = 0; ww < NW; ww++) s += PW[ww * CC + tid];
            g_mean_part[(bn * MCH + ch) * CC + tid] = s;
            __threadfence();
            __syncthreads();
            if (tid == 0) {
                atomicAdd(&g_meanbn_done[bn], 1u);
                atomicAdd(&g_meanb_done[bn / NN], 1u);
            }
        } else if (task < T1E) {
            // ===== T1: plain prototype =====
            int bn = task - T0E;
            float xm = x_shot[(size_t)bn * CC + tid];  // KK=1
            float r[1] = {xm * xm};
            warpRed<1>(r);
            if (lane == 0) dyn[w] = r[0];
            __syncthreads();
            float tot = 0.0f;
#pragma unroll
            for (int ww = 0; ww < NW; ww++) tot += dyn[ww];
            g_xs2_hat[bn * CC + tid] = xm / fmaxf(sqrtf(tot), 1e-12f);
            signal1(&g_shot_done);
        } else if (task < T2E) {
            // ===== T2: MLP partials (prefetch, wait only needed means) =====
            int s2 = task - T1E;
            int row = s2 / HCH, ch = s2 % HCH;
            float* SX = dyn; float* HP = dyn + CC; float* HID = dyn + CC + 8*HCW;
            const float *w1, *b1, *w2;
            if (row < BB) { w1 = w1t; b1 = b1t; w2 = w2t; }
            else          { w1 = w1c; b1 = b1c; w2 = w2c; }

            int ce = tid / 48, jp = tid % 48, j0 = ch * HCW;
            const float* w1b = w1 + j0 + jp * 2;
            const float* w2p = w2 + (size_t)j0 * CC + tid;
#pragma unroll 8
            for (int c = 0; c < 48; c++) pfL2(w1b + (size_t)(ce * 48 + c) * HH);
#pragma unroll 8
            for (int j = ce; j < HCW; j += 8) pfL2(w2p + (size_t)j * CC);

            if (tid == 0) {
                if (row < BB) {
                    while (*(volatile unsigned*)&g_meanb_done[row] < (unsigned)(NN*MCH)) __nanosleep(32);
                } else {
                    while (*(volatile unsigned*)&g_meanbn_done[row - BB] < (unsigned)MCH) __nanosleep(32);
                }
            }
            __syncthreads();

            if (row < BB) {
                float s = 0.0f;
#pragma unroll
                for (int n = 0; n < NN; n++)
#pragma unroll
                    for (int c2 = 0; c2 < MCH; c2++)
                        s += g_mean_part[((row * NN + n) * MCH + c2) * CC + tid];
                SX[tid] = s * (1.0f / (KT * NN));
            } else {
                int r = row - BB;
                float s = 0.0f;
#pragma unroll
                for (int c2 = 0; c2 < MCH; c2++)
                    s += g_mean_part[(r * MCH + c2) * CC + tid];
                SX[tid] = s * (1.0f / KT);
            }
            __syncthreads();

            u64 hp2 = 0ull;
#pragma unroll 8
            for (int c = 0; c < 48; c++) {
                float x = SX[ce * 48 + c];
                u64 wv = *(const u64*)(w1b + (size_t)(ce * 48 + c) * HH);
                ffma2(hp2, pk2(x, x), wv);
            }
            {
                float h0, h1;
                unpk2(hp2, h0, h1);
                HP[ce * HCW + jp * 2]     = h0;
                HP[ce * HCW + jp * 2 + 1] = h1;
            }
            __syncthreads();
            if (tid < HCW) {
                float s = b1[j0 + tid];
#pragma unroll
                for (int e = 0; e < 8; e++) s += HP[e * HCW + tid];
                HID[tid] = fmaxf(s, 0.0f);
            }
            __syncthreads();

            float o = 0.0f;
#pragma unroll 8
            for (int j = 0; j < HCW; j++) o += HID[j] * w2p[(size_t)j * CC];
            g_mlp_part[(size_t)s2 * CC + tid] = o;
            signal1(&g_mlprow_done[row]);
        } else if (task < T3E) {
            // ===== T3: MLP finish (own row only) =====
            int row = task - T2E;
            waitCnt(&g_mlprow_done[row], HCH);
            float o = (row < BB) ? b2t[tid] : b2c[tid];
#pragma unroll
            for (int c2 = 0; c2 < HCH; c2++)
                o += g_mlp_part[(size_t)(row * HCH + c2) * CC + tid];
            if (row < BB) g_wt[row * CC + tid] = o;
            else          g_wc[(row - BB) * CC + tid] = sigm(o);
            signal1(&g_wcwt_done);
        } else if (task < TAE) {
            // ===== T5a: num dots + SIM/mx — NO dependency until the tail =====
            int m = task - T3E;
            int b = m / (NCHK * NQG);
            int rem = m % (NCHK * NQG);
            int chunk = rem / NQG, qg = rem % NQG;
            int t0c = chunk * TQ;
            int q0 = b * QQ + qg * QG;
            float* SIMN = dyn;                  // QG*NN*TQ raw numerators
            float* NQV  = dyn + QG*NN*TQ;       // QG*TQ |fq| values
            float* NSS  = NQV + QG*TQ;          // NN*TQ

            const int g8 = lane >> 3, l8 = lane & 7;
            for (int base = w * 4; base < QG * TQ; base += NW * 4) {
                int item = base + g8;
                bool valid = item < QG * TQ;
                int it = valid ? item : QG * TQ - 1;
                int trel = it / QG, qi = it % QG;
                const float* fp = fq + ((size_t)(q0 + qi) * TT + t0c + trel) * CC + l8 * 4;
                const float* sp = fshot + (((size_t)(b * NN)) * KT + t0c + trel) * CC + l8 * 4;
                u64 rp[6];
#pragma unroll
                for (int k = 0; k < 6; k++) rp[k] = 0ull;
#pragma unroll 4
                for (int i = 0; i < 12; i++) {
                    ulonglong2 a = *(const ulonglong2*)(fp + i * 32);
                    ffma2(rp[0], a.x, a.x);
                    ffma2(rp[0], a.y, a.y);
#pragma unroll
                    for (int n = 0; n < NN; n++) {
                        ulonglong2 u = *(const ulonglong2*)(sp + n * NSTRIDE + i * 32);
                        ffma2(rp[1 + n], a.x, u.x);
                        ffma2(rp[1 + n], a.y, u.y);
                    }
                }
                float r[6];
#pragma unroll
                for (int k = 0; k < 6; k++) r[k] = upsum(rp[k]);
                segRed8<6>(r);
                if (l8 == 0 && valid) {
                    NQV[qi * TQ + trel] = sqrtf(r[0]);
#pragma unroll
                    for (int n = 0; n < NN; n++)
                        SIMN[(qi * NN + n) * TQ + trel] = r[1 + n];
                }
            }
            // tail: now wait for ns of this batch
            waitCnt(&g_meanb_done[b], NN*MCH);
            if (tid < NN * TQ) {
                int n = tid / TQ, t = tid % TQ;
                NSS[tid] = g_ns[(b * NN + n) * KT + t0c + t];
            }
            __syncthreads();
            if (tid < QG * NN) {
                int qi = tid / NN, n = tid % NN;
                float mm = -3.4e38f;
#pragma unroll
                for (int t = 0; t < TQ; t++) {
                    float den = fmaxf(NQV[qi * TQ + t] * NSS[n * TQ + t], 1e-8f);
                    mm = fmaxf(mm, SIMN[(qi * NN + n) * TQ + t] / den);
                }
                g_mx_part[((size_t)chunk * BQ + q0 + qi) * NN + n] = mm;
            }
            __threadfence();
            __syncthreads();
            if (tid < QG) atomicAdd(&g_bq_done[q0 + tid], 1u);
        } else if (task < TBE) {
            // ===== T5b: map_q dots + smq (waits wc/wt) =====
            int m = task - TAE;
            int b = m / (NCHK * NQG);
            int rem = m % (NCHK * NQG);
            int chunk = rem / NQG, qg = rem % NQG;
            int t0c = chunk * TQ;
            int q0 = b * QQ + qg * QG;
            float* VV = dyn;                    // NN*CC
            waitCnt(&g_wcwt_done, NFIN);
            {
                float wtb = g_wt[b * CC + tid];
#pragma unroll
                for (int n = 0; n < NN; n++)
                    VV[n * CC + tid] = g_wc[(b * NN + n) * CC + tid] * wtb;
            }
            __syncthreads();

            const int g8 = lane >> 3, l8 = lane & 7;
            for (int base = w * 4; base < QG * TQ; base += NW * 4) {
                int item = base + g8;
                bool valid = item < QG * TQ;
                int it = valid ? item : QG * TQ - 1;
                int trel = it / QG, qi = it % QG;
                const float* fp = fq + ((size_t)(q0 + qi) * TT + t0c + trel) * CC + l8 * 4;
                u64 rp[5];
#pragma unroll
                for (int k = 0; k < 5; k++) rp[k] = 0ull;
#pragma unroll 4
                for (int i = 0; i < 12; i++) {
                    ulonglong2 a = *(const ulonglong2*)(fp + i * 32);
#pragma unroll
                    for (int n = 0; n < NN; n++) {
                        ulonglong2 v = *(const ulonglong2*)(VV + n * CC + i * 32 + l8 * 4);
                        ffma2(rp[n], a.x, v.x);
                        ffma2(rp[n], a.y, v.y);
                    }
                }
                float r[5];
#pragma unroll
                for (int k = 0; k < 5; k++) r[k] = upsum(rp[k]);
                segRed8<5>(r);
                if (l8 == 0 && valid) {
#pragma unroll
                    for (int n = 0; n < NN; n++)
                        g_smq[((size_t)(q0 + qi) * NN + n) * TT + t0c + trel] = sigm(r[n]);
                }
            }
            __threadfence();
            __syncthreads();
            if (tid < QG) atomicAdd(&g_bq_done[q0 + tid], 1u);
        } else if (task < T4E) {
            // ===== T4: shot map_s partials (waits wc/wt) =====
            int s2 = task - TBE;
            int bn = s2 / SCH, ch = s2 % SCH;
            int b = bn / NN;
            int t0 = ch * 40, t1 = min(KT, t0 + 40);
            float* SVV = dyn; float* PW = dyn + CC;
            waitCnt(&g_wcwt_done, NFIN);
            SVV[tid] = g_wc[bn * CC + tid] * g_wt[b * CC + tid];
            __syncthreads();

            float acc[12];
#pragma unroll
            for (int e = 0; e < 12; e++) acc[e] = 0.0f;
            for (int t = t0 + w; t < t1; t += NW) {
                const float* fp = fshot + ((size_t)bn * KT + t) * CC + 4 * lane;
                float fv[12];
#pragma unroll
                for (int j = 0; j < 3; j++) {
                    float4 u = *(const float4*)(fp + 128 * j);
                    fv[4*j] = u.x; fv[4*j+1] = u.y; fv[4*j+2] = u.z; fv[4*j+3] = u.w;
                }
                float r[1] = {0.0f};
#pragma unroll
                for (int j = 0; j < 3; j++) {
                    float4 u = *(const float4*)(&SVV[128 * j + 4 * lane]);
                    r[0] += fv[4*j]*u.x + fv[4*j+1]*u.y + fv[4*j+2]*u.z + fv[4*j+3]*u.w;
                }
                warpRed<1>(r);
                float ms = sigm(r[0]);
#pragma unroll
                for (int e = 0; e < 12; e++) acc[e] += fv[e] * ms;
            }
#pragma unroll
            for (int e = 0; e < 12; e++) {
                int c = 128 * (e >> 2) + (lane << 2) + (e & 3);
                PW[w * CC + c] = acc[e];
            }
            __syncthreads();
            float s = 0.0f;
#pragma unroll
            for (int ww = 0; ww < NW; ww++) s += PW[ww * CC + tid];
            g_shot_part[(size_t)s2 * CC + tid] = s;
            signal1(&g_shot_done);
        } else {
            // ===== T6: finals =====
            int bq = task - T4E;
            int b = bq / QQ;
            float* SMQ5 = dyn;                      // NN*TT = 980
            float* PW4  = dyn + NN*TT;              // 4*NN*CC = 7680
            float* CW   = PW4 + 4*NN*CC;            // NW*21
            float* TOT  = CW + NW*21;
            if (tid == 0) {
                while (*(volatile unsigned*)&g_shot_done < (unsigned)SHOT_TGT) __nanosleep(32);
                while (*(volatile unsigned*)&g_bq_done[bq] < (unsigned)BQ_TGT) __nanosleep(32);
            }
            __syncthreads();
            for (int i = tid; i < NN * TT; i += 384)
                SMQ5[i] = g_smq[(size_t)bq * NN * TT + i];
            __syncthreads();

            if (tid == 0) {
                float s = 0.0f;
#pragma unroll
                for (int n = 0; n < NN; n++) {
                    float mm = -3.4e38f;
                    for (int ch = 0; ch < NCHK; ch++)
                        mm = fmaxf(mm, g_mx_part[((size_t)ch * BQ + bq) * NN + n]);
                    s += mm;
                }
                s *= (1.0f / NN);
                out[bq] = s;
                out[BQ + bq] = s;
            }

            {
                int tq = tid / 96, c4 = tid % 96;
                u64 accp[NN][2];
#pragma unroll
                for (int n = 0; n < NN; n++) { accp[n][0] = 0ull; accp[n][1] = 0ull; }
                const float* fp4 = fq + ((size_t)bq * TT + tq * 49) * CC + c4 * 4;
#pragma unroll 7
                for (int t = 0; t < 49; t++) {
                    ulonglong2 a = *(const ulonglong2*)(fp4 + (size_t)t * CC);
#pragma unroll
                    for (int n = 0; n < NN; n++) {
                        float s = SMQ5[n * TT + tq * 49 + t];
                        u64 ss = pk2(s, s);
                        ffma2(accp[n][0], a.x, ss);
                        ffma2(accp[n][1], a.y, ss);
                    }
                }
#pragma unroll
                for (int n = 0; n < NN; n++) {
                    float l0, h0, l1, h1;
                    unpk2(accp[n][0], l0, h0);
                    unpk2(accp[n][1], l1, h1);
                    float* p = PW4 + (tq * NN + n) * CC + c4 * 4;
                    p[0] = l0; p[1] = h0; p[2] = l1; p[3] = h1;
                }
            }
            __syncthreads();

            float acc[NN];
#pragma unroll
            for (int n = 0; n < NN; n++) {
                float s = 0.0f;
#pragma unroll
                for (int q2 = 0; q2 < 4; q2++) s += PW4[(q2 * NN + n) * CC + tid];
                acc[n] = s;
            }

            float xqv = xq_in[(size_t)bq * CC + tid];
            float pv[21];
            pv[0] = xqv * xqv;
#pragma unroll
            for (int n = 0; n < NN; n++) {
                float wcv = g_wc[(b * NN + n) * CC + tid];
                float sp = 0.0f;
#pragma unroll
                for (int ch = 0; ch < SCH; ch++)
                    sp += g_shot_part[(size_t)((b * NN + n) * SCH + ch) * CC + tid];
                float xsr = wcv * sp * (1.0f / KT);
                float xqr = wcv * acc[n] * (1.0f / TT);
                pv[1 + n]  = xqv * g_xs2_hat[(b * NN + n) * CC + tid];
                pv[6 + n]  = xqr * xqr;
                pv[11 + n] = xqr * xsr;
                pv[16 + n] = xsr * xsr;
            }
            warpRed<21>(pv);
            if (lane == 0) {
#pragma unroll
                for (int k = 0; k < 21; k++) CW[w * 21 + k] = pv[k];
            }
            __syncthreads();
            if (tid < 21) {
                float s = 0.0f;
#pragma unroll
                for (int ww = 0; ww < NW; ww++) s += CW[ww * 21 + tid];
                TOT[tid] = s;
            }
            __syncthreads();
            if (tid < NN) {
                float nq2 = fmaxf(sqrtf(TOT[0]), 1e-12f);
                out[2 * BQ + bq * NN + tid] = TEMPF * TOT[1 + tid] / nq2;
                out[2 * BQ + BQ * NN + bq * NN + tid] =
                    TOT[11 + tid] / ((1e-16f + sqrtf(TOT[6 + tid])) * (1e-16f + sqrtf(TOT[16 + tid])));
            }
        }
    }

    // drain, then reset all counters for next graph replay
    gridBar();
    if (blockIdx.x == 0) {
        if (tid < BQ) g_bq_done[tid] = 0u;
        if (tid < BB*NN) g_meanbn_done[tid] = 0u;
        if (tid < NFIN) g_mlprow_done[tid] = 0u;
        if (tid < BB) g_meanb_done[tid] = 0u;
        if (tid == 0) {
            g_wcwt_done = 0u; g_shot_done = 0u; g_task = 0u;
        }
    }
}

extern "C" void kernel_launch(void* const* d_in, const int* in_sizes, int n_in,
                              void* d_out, int out_size) {
    const float* feat_shot  = (const float*)d_in[0];
    const float* feat_query = (const float*)d_in[1];
    const float* x_shot     = (const float*)d_in[2];
    const float* x_query    = (const float*)d_in[3];
    const float* w1_task    = (const float*)d_in[4];
    const float* b1_task    = (const float*)d_in[5];
    const float* w2_task    = (const float*)d_in[6];
    const float* b2_task    = (const float*)d_in[7];
    const float* w1_cls     = (const float*)d_in[8];
    const float* b1_cls     = (const float*)d_in[9];
    const float* w2_cls     = (const float*)d_in[10];
    const float* b2_cls     = (const float*)d_in[11];
    float* out = (float*)d_out;

    cudaFuncSetAttribute(kFused, cudaFuncAttributeMaxDynamicSharedMemorySize, DYN_BYTES);

    int dev = 0;
    cudaGetDevice(&dev);
    int sms = 0;
    cudaDeviceGetAttribute(&sms, cudaDevAttrMultiProcessorCount, dev);
    int maxBlk = 1;
    cudaOccupancyMaxActiveBlocksPerMultiprocessor(&maxBlk, kFused, 384, DYN_BYTES);
    if (maxBlk < 1) maxBlk = 1;
    int grid = sms * maxBlk;

    kFused<<<grid, 384, DYN_BYTES>>>(feat_shot, feat_query, x_shot, x_query,
                                     w1_task, b1_task, w2_task, b2_task,
                                     w1_cls, b1_cls, w2_cls, b2_cls, out);
}